// round 8
// baseline (speedup 1.0000x reference)
#include <cuda_runtime.h>
#include <math.h>

typedef unsigned long long u64;
#define DINL __device__ __forceinline__

#define JSPLIT 4
#define OUTEL  2097152            // 4*2048*256

// ---------------- scratch ----------------
static __device__ float g_feats[4*4*2048*64];     // [b][h][n][64]
static __device__ float g_ss [32768];             // [bh][n] self score
static __device__ float g_Fa [32768];             // e^{sn}
static __device__ float g_Fb [32768];             // e^{0.2 sn}
static __device__ float g_thr[32768];             // e^{-ss}
static __device__ float g_EaZ[32768];             // e^{ss}/z
static __device__ float g_EbZ[32768];             // e^{0.2 ss}/z
static __device__ float g_part[JSPLIT*OUTEL];
static __device__ float g_psum[1024];
static __device__ int   g_pcd[1024];
static __device__ int   g_pca[1024];
static __device__ int   g_mflag;                  // nonzero-mask flag

// ---------------- f32x2 helpers ----------------
DINL u64 pk2(float a, float b){ u64 r; asm("mov.b64 %0, {%1, %2};" : "=l"(r) : "f"(a), "f"(b)); return r; }
DINL void fma2(u64& d, u64 a, u64 b){ asm("fma.rn.f32x2 %0, %1, %2, %0;" : "+l"(d) : "l"(a), "l"(b)); }
DINL float2 upk(u64 v){ float2 r; asm("mov.b64 {%0, %1}, %2;" : "=f"(r.x), "=f"(r.y) : "l"(v)); return r; }

// ================= kernel 1: feats = x @ W[h] =================
__global__ void __launch_bounds__(256) k_feats(const float* __restrict__ x,
                                               const float* __restrict__ W){
    __shared__ float Ws[64*64];
    __shared__ float Xs[64*64];
    int b = blockIdx.z, h = blockIdx.y, it = blockIdx.x, t = threadIdx.x;
    if (b == 0 && h == 0 && it == 0 && t == 0) g_mflag = 0;   // per-launch reset
    const float* wsrc = W + h*4096;
    const float* xsrc = x + (b*2048 + it*64)*64;
    for (int e = t; e < 4096; e += 256){ Ws[e] = wsrc[e]; Xs[e] = xsrc[e]; }
    __syncthreads();
    int k = t & 63, rg = t >> 6;
    float acc[16];
    #pragma unroll
    for (int r = 0; r < 16; r++) acc[r] = 0.f;
    #pragma unroll 8
    for (int f = 0; f < 64; f++){
        float wf = Ws[f*64 + k];
        #pragma unroll
        for (int r = 0; r < 16; r++) acc[r] += Xs[(rg*16 + r)*64 + f] * wf;
    }
    float* fo = g_feats + ((b*4 + h)*2048 + it*64)*64;
    #pragma unroll
    for (int r = 0; r < 16; r++) fo[(rg*16 + r)*64 + k] = acc[r];
}

// ================= kernel 2: scores + factorized exps =================
__global__ void __launch_bounds__(256) k_scores(const float* __restrict__ a_self,
                                                const float* __restrict__ a_neigh){
    int t = threadIdx.x, w = t >> 5, lane = t & 31;
    int row = blockIdx.x*8 + w;              // (b,h,n)
    int bh = row >> 11, h = bh & 3;
    const float* fr = g_feats + (size_t)row*64;
    float f0 = fr[lane], f1 = fr[lane + 32];
    float ss = f0*a_self[h*64 + lane]  + f1*a_self[h*64 + lane + 32];
    float sn = f0*a_neigh[h*64 + lane] + f1*a_neigh[h*64 + lane + 32];
    #pragma unroll
    for (int o = 16; o > 0; o >>= 1){
        ss += __shfl_xor_sync(0xffffffffu, ss, o);
        sn += __shfl_xor_sync(0xffffffffu, sn, o);
    }
    if (lane == 0){
        g_ss[row] = ss;
        g_Fa[row] = __expf(sn);
        g_Fb[row] = __expf(0.2f*sn);
    }
}

// ================= kernel 3: Z per (b,h,i) via factorization; mask flag =================
// warp per (b,i) row, all 4 heads; Fa/Fb staged in smem in two j-halves.
// grid 1024 = 4b * 256 rowchunks, 256 threads
__global__ void __launch_bounds__(256) k_mz(const float* __restrict__ mask){
    __shared__ float FaT[4][1024];
    __shared__ float FbT[4][1024];
    int b = blockIdx.x >> 8, rc = blockIdx.x & 255;
    int t = threadIdx.x, w = t >> 5, lane = t & 31;
    int i = rc*8 + w;
    float ss[4], thr[4];
    float zA[4] = {0,0,0,0}, zB[4] = {0,0,0,0};
    #pragma unroll
    for (int h = 0; h < 4; h++){
        ss[h]  = g_ss[(b*4 + h)*2048 + i];
        thr[h] = __expf(-ss[h]);
    }
    const float4* mrow = (const float4*)(mask + ((size_t)b*2048 + i)*2048);
    bool anym = false;
    for (int half = 0; half < 2; half++){
        __syncthreads();
        for (int e = t; e < 4096; e += 256){
            int h = e >> 10, j = e & 1023;
            FaT[h][j] = g_Fa[(b*4 + h)*2048 + half*1024 + j];
            FbT[h][j] = g_Fb[(b*4 + h)*2048 + half*1024 + j];
        }
        __syncthreads();
        for (int q = lane; q < 256; q += 32){
            float4 mk = mrow[half*256 + q];
            float e0 = 1.f, e1 = 1.f, e2 = 1.f, e3 = 1.f;
            if (mk.x != 0.f){ e0 = __expf(mk.x); anym = true; }
            if (mk.y != 0.f){ e1 = __expf(mk.y); anym = true; }
            if (mk.z != 0.f){ e2 = __expf(mk.z); anym = true; }
            if (mk.w != 0.f){ e3 = __expf(mk.w); anym = true; }
            #pragma unroll
            for (int h = 0; h < 4; h++){
                float4 fa = *(const float4*)&FaT[h][q*4];
                float4 fb = *(const float4*)&FbT[h][q*4];
                if (fa.x > thr[h]) zA[h] += fa.x*e0; else zB[h] += fb.x*e0;
                if (fa.y > thr[h]) zA[h] += fa.y*e1; else zB[h] += fb.y*e1;
                if (fa.z > thr[h]) zA[h] += fa.z*e2; else zB[h] += fb.z*e2;
                if (fa.w > thr[h]) zA[h] += fa.w*e3; else zB[h] += fb.w*e3;
            }
        }
    }
    #pragma unroll
    for (int o = 16; o > 0; o >>= 1){
        #pragma unroll
        for (int h = 0; h < 4; h++){
            zA[h] += __shfl_xor_sync(0xffffffffu, zA[h], o);
            zB[h] += __shfl_xor_sync(0xffffffffu, zB[h], o);
        }
    }
    if (lane == 0){
        #pragma unroll
        for (int h = 0; h < 4; h++){
            float Ea = __expf(ss[h]), Eb = __expf(0.2f*ss[h]);
            float z = Ea*zA[h] + Eb*zB[h];
            int idx = (b*4 + h)*2048 + i;
            g_thr[idx] = thr[h];
            g_EaZ[idx] = Ea / z;
            g_EbZ[idx] = Eb / z;
        }
    }
    if (anym) atomicOr(&g_mflag, 1);
}

// ================= kernel 4: P = factorized softmax * adj ; partial = P @ feats =================
// grid (64,4,4): x = js*16+it, y=h, z=b; 256 threads; thread tile 8i(4 f32x2) x 4k
__global__ void __launch_bounds__(256, 4) k_main(const float* __restrict__ adj,
                                                 const float* __restrict__ mask){
    __shared__ float Ps[32*130];     // [j][i] pad 130
    __shared__ float Fs[32*64];      // [j][k]
    __shared__ float FaS[512], FbS[512];
    __shared__ float thrS[128], EaZS[128], EbZS[128];
    __shared__ float rS[256];
    __shared__ int   rD[256], rA[256];

    int b = blockIdx.z, h = blockIdx.y;
    int js = blockIdx.x >> 4, it = blockIdx.x & 15;
    int t = threadIdx.x;
    int bh = b*4 + h;
    int jbase = js*512;
    for (int e = t; e < 512; e += 256){
        FaS[e] = g_Fa[bh*2048 + jbase + e];
        FbS[e] = g_Fb[bh*2048 + jbase + e];
    }
    if (t < 128){
        int gi = bh*2048 + it*128 + t;
        thrS[t] = g_thr[gi]; EaZS[t] = g_EaZ[gi]; EbZS[t] = g_EbZ[gi];
    }
    const bool mz = (g_mflag == 0);

    int kg = t & 15, ig = t >> 4;
    int k0 = kg*4,  i0 = ig*8;
    u64 acc[4][4];
    #pragma unroll
    for (int a = 0; a < 4; a++)
        #pragma unroll
        for (int c = 0; c < 4; c++) acc[a][c] = 0ull;

    int jl = t & 31, ib = t >> 5;
    float sumD = 0.f; int cntD = 0, cntA = 0;
    const float* fbase = g_feats + (size_t)bh*2048*64;
    int rowbase = (b*2048 + it*128)*2048 + jbase + jl;   // + i*2048 + jt*32

    #pragma unroll 1
    for (int jt = 0; jt < 16; jt++){
        __syncthreads();
        // ---- Phase A: factorized P tile (128 x 32) ----
        float fa = FaS[jt*32 + jl];
        float fb = FbS[jt*32 + jl];
        int gb = rowbase + jt*32;
        #pragma unroll
        for (int p = 0; p < 8; p++){
            int i = (p*8 + ib)*2;
            int gidx = gb + i*2048;
            float a0 = adj[gidx], a1 = adj[gidx + 2048];
            float w0 = (fa > thrS[i]  ) ? EaZS[i]  *fa : EbZS[i]  *fb;
            float w1 = (fa > thrS[i+1]) ? EaZS[i+1]*fa : EbZS[i+1]*fb;
            float pd0 = a0 * w0;
            float pd1 = a1 * w1;
            if (!mz){                       // general-mask fallback (never taken when mask==0)
                pd0 *= __expf(mask[gidx]);
                pd1 *= __expf(mask[gidx + 2048]);
            }
            *(u64*)&Ps[jl*130 + i] = pk2(pd0, pd1);
            sumD += fabsf(pd0) + fabsf(pd1);
            cntD += (pd0 != 0.f) + (pd1 != 0.f);
            cntA += (a0  != 0.f) + (a1  != 0.f);
        }
        // ---- feats tile ----
        const float4* fsrc = (const float4*)(fbase + (size_t)(jbase + jt*32)*64);
        ((float4*)Fs)[t]       = fsrc[t];
        ((float4*)Fs)[t + 256] = fsrc[t + 256];
        __syncthreads();
        // ---- Phase B: FFMA2 GEMM ----
        #pragma unroll 8
        for (int j = 0; j < 32; j++){
            float4 v = *(const float4*)&Fs[j*64 + k0];
            u64 v0 = pk2(v.x, v.x), v1 = pk2(v.y, v.y);
            u64 v2 = pk2(v.z, v.z), v3 = pk2(v.w, v.w);
            const float* pr = &Ps[j*130 + i0];
            u64 p0 = *(const u64*)(pr);
            u64 p1 = *(const u64*)(pr + 2);
            u64 p2 = *(const u64*)(pr + 4);
            u64 p3 = *(const u64*)(pr + 6);
            fma2(acc[0][0], p0, v0); fma2(acc[0][1], p0, v1); fma2(acc[0][2], p0, v2); fma2(acc[0][3], p0, v3);
            fma2(acc[1][0], p1, v0); fma2(acc[1][1], p1, v1); fma2(acc[1][2], p1, v2); fma2(acc[1][3], p1, v3);
            fma2(acc[2][0], p2, v0); fma2(acc[2][1], p2, v1); fma2(acc[2][2], p2, v2); fma2(acc[2][3], p2, v3);
            fma2(acc[3][0], p3, v0); fma2(acc[3][1], p3, v1); fma2(acc[3][2], p3, v2); fma2(acc[3][3], p3, v3);
        }
    }

    // ---- write partial ----
    float* po = g_part + (size_t)js*OUTEL;
    #pragma unroll
    for (int ip = 0; ip < 4; ip++){
        float2 e0 = upk(acc[ip][0]), e1 = upk(acc[ip][1]);
        float2 e2 = upk(acc[ip][2]), e3 = upk(acc[ip][3]);
        int r0 = it*128 + i0 + 2*ip;
        float4 o0 = {e0.x, e1.x, e2.x, e3.x};
        float4 o1 = {e0.y, e1.y, e2.y, e3.y};
        *(float4*)&po[(size_t)(b*2048 + r0    )*256 + h*64 + k0] = o0;
        *(float4*)&po[(size_t)(b*2048 + r0 + 1)*256 + h*64 + k0] = o1;
    }

    // ---- deterministic block reduce of loss stats ----
    rS[t] = sumD; rD[t] = cntD; rA[t] = cntA;
    __syncthreads();
    #pragma unroll
    for (int s = 128; s > 0; s >>= 1){
        if (t < s){ rS[t] += rS[t + s]; rD[t] += rD[t + s]; rA[t] += rA[t + s]; }
        __syncthreads();
    }
    if (t == 0){
        int pb = ((bh*16 + it)*4) + js;
        g_psum[pb] = rS[0]; g_pcd[pb] = rD[0]; g_pca[pb] = rA[0];
    }
}

// ================= kernel 5: combine partials + bias + BN + relu =================
__global__ void __launch_bounds__(256) k_epi(const float* __restrict__ bias,
                                             float* __restrict__ out){
    const float SC = 0.9995003746877732f;   // 1/sqrt(1.001)
    int idx = blockIdx.x*256 + threadIdx.x;
    int hk = (idx*4) & 255;
    const float4* p = (const float4*)g_part;
    float4 s0 = p[idx];
    float4 s1 = p[idx +   OUTEL/4];
    float4 s2 = p[idx + 2*OUTEL/4];
    float4 s3 = p[idx + 3*OUTEL/4];
    float4 bi = *(const float4*)&bias[hk];
    float4 o;
    o.x = fmaxf((s0.x + s1.x + s2.x + s3.x + bi.x)*SC, 0.f);
    o.y = fmaxf((s0.y + s1.y + s2.y + s3.y + bi.y)*SC, 0.f);
    o.z = fmaxf((s0.z + s1.z + s2.z + s3.z + bi.z)*SC, 0.f);
    o.w = fmaxf((s0.w + s1.w + s2.w + s3.w + bi.w)*SC, 0.f);
    ((float4*)out)[idx] = o;
}

// ================= kernel 6: finalize aux losses =================
__global__ void k_loss(float* __restrict__ out){
    int b = threadIdx.x;
    if (b < 4){
        float s = 0.f; int d = 0, a = 0;
        for (int p = 0; p < 256; p++){
            int idx = b*256 + p;
            s += g_psum[idx]; d += g_pcd[idx]; a += g_pca[idx];
        }
        out[OUTEL + b]     = (float)(d - a) * (1.f/2048.f);
        out[OUTEL + 4 + b] = s * (1.f/2048.f);
    }
}

// ================= launch =================
extern "C" void kernel_launch(void* const* d_in, const int* in_sizes, int n_in,
                              void* d_out, int out_size){
    const float* x       = (const float*)d_in[0];
    const float* adj     = (const float*)d_in[1];
    const float* mask    = (const float*)d_in[2];
    const float* W       = (const float*)d_in[3];
    const float* a_self  = (const float*)d_in[4];
    const float* a_neigh = (const float*)d_in[5];
    const float* bias    = (const float*)d_in[6];
    float* out = (float*)d_out;

    k_feats <<<dim3(32, 4, 4), 256>>>(x, W);
    k_scores<<<4096, 256>>>(a_self, a_neigh);
    k_mz    <<<1024, 256>>>(mask);
    k_main  <<<dim3(64, 4, 4), 256>>>(adj, mask);
    k_epi   <<<2048, 256>>>(bias, out);
    k_loss  <<<1, 32>>>(out);
}

// round 10
// speedup vs baseline: 1.2553x; 1.2553x over previous
#include <cuda_runtime.h>
#include <cuda_bf16.h>
#include <math.h>
#include <stdint.h>

typedef unsigned long long u64;
typedef unsigned int u32;
#define DINL __device__ __forceinline__

#define JSPLIT 4
#define OUTEL  2097152            // 4*2048*256

// ---------------- scratch ----------------
static __device__ float g_feats[4*4*2048*64];     // [bh][n][64] fp32
static __device__ float g_ss [32768];
static __device__ float g_Fa [32768];             // e^{sn}
static __device__ float g_Fb [32768];             // e^{0.2 sn}
static __device__ float g_thr[32768];             // e^{-ss}
static __device__ float g_EaZ[32768];
static __device__ float g_EbZ[32768];
static __device__ float g_part[JSPLIT*OUTEL];
static __device__ float g_psum[1024];
static __device__ int   g_pcd[1024];
static __device__ int   g_pca[1024];
static __device__ int   g_mflag;
// B fragments, fragment-ordered: [bh][jc=64][hi:1024 | lo:1024] u32
// hi-plane index: ((ks*8 + nt)*32 + lane)*2 + r
static __device__ u32   g_fB[16*64*2048];

// ---------------- mma.sync m16n8k16 bf16 (arch-neutral PTX, HMMA path) ----------------
DINL void mma16816(float* d, const u32* a, u32 b0, u32 b1){
    asm volatile(
        "mma.sync.aligned.m16n8k16.row.col.f32.bf16.bf16.f32 "
        "{%0,%1,%2,%3}, {%4,%5,%6,%7}, {%8,%9}, {%0,%1,%2,%3};"
        : "+f"(d[0]), "+f"(d[1]), "+f"(d[2]), "+f"(d[3])
        : "r"(a[0]), "r"(a[1]), "r"(a[2]), "r"(a[3]), "r"(b0), "r"(b1));
}
// split float pair into packed bf16 hi + lo (residual)
DINL void split2(float p0, float p1, u32& hi, u32& lo){
    __nv_bfloat162 hh = __float22bfloat162_rn(make_float2(p0, p1));
    float2 bk = __bfloat1622float2(hh);
    __nv_bfloat162 ll = __float22bfloat162_rn(make_float2(p0 - bk.x, p1 - bk.y));
    hi = *(u32*)&hh; lo = *(u32*)&ll;
}

// ================= kernel 1: feats = x @ W[h] =================
__global__ void __launch_bounds__(256) k_feats(const float* __restrict__ x,
                                               const float* __restrict__ W){
    __shared__ float Ws[64*64];
    __shared__ float Xs[64*64];
    int b = blockIdx.z, h = blockIdx.y, it = blockIdx.x, t = threadIdx.x;
    if (b == 0 && h == 0 && it == 0 && t == 0) g_mflag = 0;
    const float* wsrc = W + h*4096;
    const float* xsrc = x + (b*2048 + it*64)*64;
    for (int e = t; e < 4096; e += 256){ Ws[e] = wsrc[e]; Xs[e] = xsrc[e]; }
    __syncthreads();
    int k = t & 63, rg = t >> 6;
    float acc[16];
    #pragma unroll
    for (int r = 0; r < 16; r++) acc[r] = 0.f;
    #pragma unroll 8
    for (int f = 0; f < 64; f++){
        float wf = Ws[f*64 + k];
        #pragma unroll
        for (int r = 0; r < 16; r++) acc[r] += Xs[(rg*16 + r)*64 + f] * wf;
    }
    float* fo = g_feats + ((b*4 + h)*2048 + it*64)*64;
    #pragma unroll
    for (int r = 0; r < 16; r++) fo[(rg*16 + r)*64 + k] = acc[r];
}

// ================= kernel 1b: build fragment-ordered bf16 hi/lo B tiles =================
// grid (64 jc, 16 bh), 256 threads.
__global__ void __launch_bounds__(256) k_fprep(){
    __shared__ float Ft[32*64];          // feats rows jc*32..+31, all 64 feat cols
    int jc = blockIdx.x, bh = blockIdx.y, t = threadIdx.x;
    const float* src = g_feats + ((size_t)bh*2048 + jc*32)*64;
    for (int e = t; e < 2048; e += 256) Ft[e] = src[e];
    __syncthreads();
    u32* dst = g_fB + ((size_t)bh*64 + jc)*2048;
    #pragma unroll
    for (int q = 0; q < 4; q++){
        int e = q*256 + t;               // 0..1023 hi-plane entry
        int ks   = e >> 9;
        int nt   = (e >> 6) & 7;
        int lane = (e >> 1) & 31;
        int r    = e & 1;
        int g = lane >> 2, tt = lane & 3;
        int jl = ks*16 + r*8 + 2*tt;     // local j row (0..31)
        int n  = nt*8 + g;               // feature col
        float v0 = Ft[jl*64 + n];
        float v1 = Ft[(jl + 1)*64 + n];
        u32 hi, lo; split2(v0, v1, hi, lo);
        dst[e]        = hi;
        dst[1024 + e] = lo;
    }
}

// ================= kernel 2: scores + factorized exps =================
__global__ void __launch_bounds__(256) k_scores(const float* __restrict__ a_self,
                                                const float* __restrict__ a_neigh){
    int t = threadIdx.x, w = t >> 5, lane = t & 31;
    int row = blockIdx.x*8 + w;
    int bh = row >> 11, h = bh & 3;
    const float* fr = g_feats + (size_t)row*64;
    float f0 = fr[lane], f1 = fr[lane + 32];
    float ss = f0*a_self[h*64 + lane]  + f1*a_self[h*64 + lane + 32];
    float sn = f0*a_neigh[h*64 + lane] + f1*a_neigh[h*64 + lane + 32];
    #pragma unroll
    for (int o = 16; o > 0; o >>= 1){
        ss += __shfl_xor_sync(0xffffffffu, ss, o);
        sn += __shfl_xor_sync(0xffffffffu, sn, o);
    }
    if (lane == 0){
        g_ss[row] = ss;
        g_Fa[row] = __expf(sn);
        g_Fb[row] = __expf(0.2f*sn);
    }
}

// ================= kernel 3: Z per (b,h,i); mask flag =================
__global__ void __launch_bounds__(256) k_mz(const float* __restrict__ mask){
    __shared__ float FaT[4][1024];
    __shared__ float FbT[4][1024];
    int b = blockIdx.x >> 8, rc = blockIdx.x & 255;
    int t = threadIdx.x, w = t >> 5, lane = t & 31;
    int i = rc*8 + w;
    float ss[4], thr[4];
    float zA[4] = {0,0,0,0}, zB[4] = {0,0,0,0};
    #pragma unroll
    for (int h = 0; h < 4; h++){
        ss[h]  = g_ss[(b*4 + h)*2048 + i];
        thr[h] = __expf(-ss[h]);
    }
    const float4* mrow = (const float4*)(mask + ((size_t)b*2048 + i)*2048);
    bool anym = false;
    for (int half = 0; half < 2; half++){
        __syncthreads();
        for (int e = t; e < 4096; e += 256){
            int h = e >> 10, j = e & 1023;
            FaT[h][j] = g_Fa[(b*4 + h)*2048 + half*1024 + j];
            FbT[h][j] = g_Fb[(b*4 + h)*2048 + half*1024 + j];
        }
        __syncthreads();
        for (int q = lane; q < 256; q += 32){
            float4 mk = mrow[half*256 + q];
            float e0 = 1.f, e1 = 1.f, e2 = 1.f, e3 = 1.f;
            if (mk.x != 0.f){ e0 = __expf(mk.x); anym = true; }
            if (mk.y != 0.f){ e1 = __expf(mk.y); anym = true; }
            if (mk.z != 0.f){ e2 = __expf(mk.z); anym = true; }
            if (mk.w != 0.f){ e3 = __expf(mk.w); anym = true; }
            #pragma unroll
            for (int h = 0; h < 4; h++){
                float4 fa = *(const float4*)&FaT[h][q*4];
                float4 fb = *(const float4*)&FbT[h][q*4];
                if (fa.x > thr[h]) zA[h] += fa.x*e0; else zB[h] += fb.x*e0;
                if (fa.y > thr[h]) zA[h] += fa.y*e1; else zB[h] += fb.y*e1;
                if (fa.z > thr[h]) zA[h] += fa.z*e2; else zB[h] += fb.z*e2;
                if (fa.w > thr[h]) zA[h] += fa.w*e3; else zB[h] += fb.w*e3;
            }
        }
    }
    #pragma unroll
    for (int o = 16; o > 0; o >>= 1){
        #pragma unroll
        for (int h = 0; h < 4; h++){
            zA[h] += __shfl_xor_sync(0xffffffffu, zA[h], o);
            zB[h] += __shfl_xor_sync(0xffffffffu, zB[h], o);
        }
    }
    if (lane == 0){
        #pragma unroll
        for (int h = 0; h < 4; h++){
            float Ea = __expf(ss[h]), Eb = __expf(0.2f*ss[h]);
            float z = Ea*zA[h] + Eb*zB[h];
            int idx = (b*4 + h)*2048 + i;
            g_thr[idx] = thr[h];
            g_EaZ[idx] = Ea / z;
            g_EbZ[idx] = Eb / z;
        }
    }
    if (anym) atomicOr(&g_mflag, 1);
}

// ================= kernel 4: P (registers) -> mma.sync bf16 3-term GEMM =================
// grid (64,4,4): x = js*16+it, y=h, z=b; 256 threads = 8 warps, warp w owns rows [16w,16w+16)
__global__ void __launch_bounds__(256, 2) k_main(const float* __restrict__ adj,
                                                 const float* __restrict__ mask){
    __shared__ __align__(16) u32 BfS[2][2048];   // fragment-ordered B tiles, double buffer
    __shared__ float FaS[512], FbS[512];
    __shared__ float rS[256];
    __shared__ int   rD[256], rA[256];

    int b = blockIdx.z, h = blockIdx.y;
    int js = blockIdx.x >> 4, it = blockIdx.x & 15;
    int t = threadIdx.x, wid = t >> 5, lane = t & 31;
    int g = lane >> 2, tt = lane & 3;
    int bh = b*4 + h;

    for (int e = t; e < 512; e += 256){
        FaS[e] = g_Fa[bh*2048 + js*512 + e];
        FbS[e] = g_Fb[bh*2048 + js*512 + e];
    }

    int r0 = it*128 + wid*16 + g;          // row within [2048] of this bh
    float thr0 = g_thr[bh*2048 + r0],     thr1 = g_thr[bh*2048 + r0 + 8];
    float eaz0 = g_EaZ[bh*2048 + r0],     eaz1 = g_EaZ[bh*2048 + r0 + 8];
    float ebz0 = g_EbZ[bh*2048 + r0],     ebz1 = g_EbZ[bh*2048 + r0 + 8];
    size_t row0 = ((size_t)(b*2048 + r0))*2048 + js*512;
    size_t row1 = row0 + (size_t)8*2048;
    const bool mz = (g_mflag == 0);

    const u32* fBsrc = g_fB + ((size_t)bh*64 + js*16)*2048;

    float acc[8][4];
    #pragma unroll
    for (int nt = 0; nt < 8; nt++)
        #pragma unroll
        for (int r = 0; r < 4; r++) acc[nt][r] = 0.f;

    float sumD = 0.f; int cntD = 0, cntA = 0;

    // ---- stage B chunk c into buffer ----
    #define STAGE_B(c) do { \
        const uint4* _s = (const uint4*)(fBsrc + (size_t)(c)*2048); \
        uint4* _d = (uint4*)BfS[(c) & 1]; \
        _d[t] = _s[t]; _d[t + 256] = _s[t + 256]; \
    } while(0)

    // ---- Phase A: compute 16 P values for chunk c into A fragments (regs) ----
    #define PHASE_A(c, AH, AL) do { \
        int _cb = (c)*32; \
        _Pragma("unroll") \
        for (int _ks = 0; _ks < 2; _ks++){ \
            _Pragma("unroll") \
            for (int _q = 0; _q < 2; _q++){ \
                int _col = _cb + _ks*16 + _q*8 + 2*tt; \
                float2 _a0 = *(const float2*)(adj + row0 + _col); \
                float2 _a1 = *(const float2*)(adj + row1 + _col); \
                float2 _fa = *(const float2*)(FaS + _col); \
                float2 _fb = *(const float2*)(FbS + _col); \
                float _w00 = (_fa.x > thr0) ? eaz0*_fa.x : ebz0*_fb.x; \
                float _w01 = (_fa.y > thr0) ? eaz0*_fa.y : ebz0*_fb.y; \
                float _w10 = (_fa.x > thr1) ? eaz1*_fa.x : ebz1*_fb.x; \
                float _w11 = (_fa.y > thr1) ? eaz1*_fa.y : ebz1*_fb.y; \
                float _p00 = _a0.x*_w00, _p01 = _a0.y*_w01; \
                float _p10 = _a1.x*_w10, _p11 = _a1.y*_w11; \
                if (!mz){ \
                    _p00 *= __expf(mask[row0 + _col]);     _p01 *= __expf(mask[row0 + _col + 1]); \
                    _p10 *= __expf(mask[row1 + _col]);     _p11 *= __expf(mask[row1 + _col + 1]); \
                } \
                sumD += fabsf(_p00) + fabsf(_p01) + fabsf(_p10) + fabsf(_p11); \
                cntD += (_p00 != 0.f) + (_p01 != 0.f) + (_p10 != 0.f) + (_p11 != 0.f); \
                cntA += (_a0.x != 0.f) + (_a0.y != 0.f) + (_a1.x != 0.f) + (_a1.y != 0.f); \
                split2(_p00, _p01, AH[_ks*4 + _q*2],     AL[_ks*4 + _q*2]); \
                split2(_p10, _p11, AH[_ks*4 + _q*2 + 1], AL[_ks*4 + _q*2 + 1]); \
            } \
        } \
    } while(0)

    // ---- 48 MMAs on one chunk ----
    #define MMA_CHUNK(c, AH, AL) do { \
        const u32* _B = BfS[(c) & 1]; \
        _Pragma("unroll") \
        for (int _ks = 0; _ks < 2; _ks++){ \
            _Pragma("unroll") \
            for (int _nt = 0; _nt < 8; _nt++){ \
                int _ix = (_ks*8 + _nt)*64 + lane*2; \
                u64 _bhp = *(const u64*)&_B[_ix]; \
                u64 _blp = *(const u64*)&_B[1024 + _ix]; \
                u32 _bh0 = (u32)_bhp, _bh1 = (u32)(_bhp >> 32); \
                u32 _bl0 = (u32)_blp, _bl1 = (u32)(_blp >> 32); \
                mma16816(acc[_nt], &AH[_ks*4], _bh0, _bh1); \
                mma16816(acc[_nt], &AL[_ks*4], _bh0, _bh1); \
                mma16816(acc[_nt], &AH[_ks*4], _bl0, _bl1); \
            } \
        } \
    } while(0)

    u32 ahA[8], alA[8], ahB[8], alB[8];

    STAGE_B(0);
    __syncthreads();                 // FaS/FbS + buf0 ready
    PHASE_A(0, ahA, alA);

    #pragma unroll 1
    for (int c = 0; c < 16; c += 2){
        STAGE_B(c + 1);
        PHASE_A(c + 1, ahB, alB);
        MMA_CHUNK(c, ahA, alA);
        __syncthreads();
        if (c + 2 < 16){
            STAGE_B(c + 2);
            PHASE_A(c + 2, ahA, alA);
        }
        MMA_CHUNK(c + 1, ahB, alB);
        __syncthreads();
    }

    // ---- epilogue: write partial tile ----
    {
        float* po = g_part + (size_t)js*OUTEL;
        size_t base = ((size_t)(b*2048 + r0))*256 + h*64 + 2*tt;
        #pragma unroll
        for (int nt = 0; nt < 8; nt++){
            *(float2*)&po[base + nt*8]            = make_float2(acc[nt][0], acc[nt][1]);
            *(float2*)&po[base + nt*8 + 8*256]    = make_float2(acc[nt][2], acc[nt][3]);
        }
    }

    // ---- deterministic stats reduce ----
    rS[t] = sumD; rD[t] = cntD; rA[t] = cntA;
    __syncthreads();
    #pragma unroll
    for (int s = 128; s > 0; s >>= 1){
        if (t < s){ rS[t] += rS[t + s]; rD[t] += rD[t + s]; rA[t] += rA[t + s]; }
        __syncthreads();
    }
    if (t == 0){
        int pb = ((bh*16 + it)*4) + js;
        g_psum[pb] = rS[0]; g_pcd[pb] = rD[0]; g_pca[pb] = rA[0];
    }
    #undef STAGE_B
    #undef PHASE_A
    #undef MMA_CHUNK
}

// ================= kernel 5: combine partials + bias + BN + relu =================
__global__ void __launch_bounds__(256) k_epi(const float* __restrict__ bias,
                                             float* __restrict__ out){
    const float SC = 0.9995003746877732f;
    int idx = blockIdx.x*256 + threadIdx.x;
    int hk = (idx*4) & 255;
    const float4* p = (const float4*)g_part;
    float4 s0 = p[idx];
    float4 s1 = p[idx +   OUTEL/4];
    float4 s2 = p[idx + 2*OUTEL/4];
    float4 s3 = p[idx + 3*OUTEL/4];
    float4 bi = *(const float4*)&bias[hk];
    float4 o;
    o.x = fmaxf((s0.x + s1.x + s2.x + s3.x + bi.x)*SC, 0.f);
    o.y = fmaxf((s0.y + s1.y + s2.y + s3.y + bi.y)*SC, 0.f);
    o.z = fmaxf((s0.z + s1.z + s2.z + s3.z + bi.z)*SC, 0.f);
    o.w = fmaxf((s0.w + s1.w + s2.w + s3.w + bi.w)*SC, 0.f);
    ((float4*)out)[idx] = o;
}

// ================= kernel 6: finalize aux losses =================
__global__ void k_loss(float* __restrict__ out){
    int b = threadIdx.x;
    if (b < 4){
        float s = 0.f; int d = 0, a = 0;
        for (int p = 0; p < 256; p++){
            int idx = b*256 + p;
            s += g_psum[idx]; d += g_pcd[idx]; a += g_pca[idx];
        }
        out[OUTEL + b]     = (float)(d - a) * (1.f/2048.f);
        out[OUTEL + 4 + b] = s * (1.f/2048.f);
    }
}

// ================= launch =================
extern "C" void kernel_launch(void* const* d_in, const int* in_sizes, int n_in,
                              void* d_out, int out_size){
    const float* x       = (const float*)d_in[0];
    const float* adj     = (const float*)d_in[1];
    const float* mask    = (const float*)d_in[2];
    const float* W       = (const float*)d_in[3];
    const float* a_self  = (const float*)d_in[4];
    const float* a_neigh = (const float*)d_in[5];
    const float* bias    = (const float*)d_in[6];
    float* out = (float*)d_out;

    k_feats <<<dim3(32, 4, 4), 256>>>(x, W);
    k_fprep <<<dim3(64, 16), 256>>>();
    k_scores<<<4096, 256>>>(a_self, a_neigh);
    k_mz    <<<1024, 256>>>(mask);
    k_main  <<<dim3(64, 4, 4), 256>>>(adj, mask);
    k_epi   <<<2048, 256>>>(bias, out);
    k_loss  <<<1, 32>>>(out);
}

// round 11
// speedup vs baseline: 1.3674x; 1.0893x over previous
#include <cuda_runtime.h>
#include <cuda_bf16.h>
#include <math.h>
#include <stdint.h>

typedef unsigned long long u64;
typedef unsigned int u32;
#define DINL __device__ __forceinline__

#define JSPLIT 4
#define OUTEL  2097152            // 4*2048*256

// ---------------- scratch ----------------
static __device__ float g_Fa [32768];             // e^{sn}
static __device__ float g_Fb [32768];             // e^{0.2 sn}
static __device__ float g_thr[32768];             // e^{-ss}
static __device__ float g_Ea [32768];             // e^{ss}
static __device__ float g_Eb [32768];             // e^{0.2 ss}
static __device__ float g_part[JSPLIT*OUTEL];     // unnormalized GEMM partials
static __device__ float g_zpart[JSPLIT*32768];    // per-row Z partials
static __device__ float g_spart[JSPLIT*32768];    // per-row sum|p~| partials
static __device__ float g_lsum[16];
static __device__ int   g_pcd[1024];
static __device__ int   g_pca[1024];
static __device__ int   g_mflag;
// B fragments, fragment-ordered: [bh][jc=64][hi:1024 | lo:1024] u32
static __device__ u32   g_fB[16*64*2048];

// ---------------- mma.sync m16n8k16 bf16 (arch-neutral PTX, HMMA path) ----------------
DINL void mma16816(float* d, const u32* a, u32 b0, u32 b1){
    asm volatile(
        "mma.sync.aligned.m16n8k16.row.col.f32.bf16.bf16.f32 "
        "{%0,%1,%2,%3}, {%4,%5,%6,%7}, {%8,%9}, {%0,%1,%2,%3};"
        : "+f"(d[0]), "+f"(d[1]), "+f"(d[2]), "+f"(d[3])
        : "r"(a[0]), "r"(a[1]), "r"(a[2]), "r"(a[3]), "r"(b0), "r"(b1));
}
DINL void split2(float p0, float p1, u32& hi, u32& lo){
    __nv_bfloat162 hh = __float22bfloat162_rn(make_float2(p0, p1));
    float2 bk = __bfloat1622float2(hh);
    __nv_bfloat162 ll = __float22bfloat162_rn(make_float2(p0 - bk.x, p1 - bk.y));
    hi = *(u32*)&hh; lo = *(u32*)&ll;
}

// ================= kernel 1: feats GEMM + scores + fragment pack (fused) =================
// grid (32, 4, 4) = (ntile64, h, b), 256 threads
__global__ void __launch_bounds__(256) k_feats(const float* __restrict__ x,
                                               const float* __restrict__ W,
                                               const float* __restrict__ a_self,
                                               const float* __restrict__ a_neigh){
    __shared__ float Ws[4096];
    __shared__ float Xs[4096];          // x tile, then reused as feats tile [64][64]
    int b = blockIdx.z, h = blockIdx.y, it = blockIdx.x, t = threadIdx.x;
    int bh = b*4 + h;
    if (b == 0 && h == 0 && it == 0 && t == 0) g_mflag = 0;
    const float* wsrc = W + h*4096;
    const float* xsrc = x + (b*2048 + it*64)*64;
    for (int e = t; e < 4096; e += 256){ Ws[e] = wsrc[e]; Xs[e] = xsrc[e]; }
    __syncthreads();
    int k = t & 63, rg = t >> 6;
    float acc[16];
    #pragma unroll
    for (int r = 0; r < 16; r++) acc[r] = 0.f;
    #pragma unroll 8
    for (int f = 0; f < 64; f++){
        float wf = Ws[f*64 + k];
        #pragma unroll
        for (int r = 0; r < 16; r++) acc[r] += Xs[(rg*16 + r)*64 + f] * wf;
    }
    __syncthreads();                    // all Xs reads done
    #pragma unroll
    for (int r = 0; r < 16; r++) Xs[(rg*16 + r)*64 + k] = acc[r];   // feats tile
    __syncthreads();

    // ---- scores: warp wid handles rows wid*8..+7 ----
    int wid = t >> 5, lane = t & 31;
    float as0 = a_self[h*64 + lane],  as1 = a_self[h*64 + lane + 32];
    float an0 = a_neigh[h*64 + lane], an1 = a_neigh[h*64 + lane + 32];
    #pragma unroll
    for (int rr = 0; rr < 8; rr++){
        int row = wid*8 + rr;
        float f0 = Xs[row*64 + lane], f1 = Xs[row*64 + lane + 32];
        float ss = f0*as0 + f1*as1;
        float sn = f0*an0 + f1*an1;
        #pragma unroll
        for (int o = 16; o > 0; o >>= 1){
            ss += __shfl_xor_sync(0xffffffffu, ss, o);
            sn += __shfl_xor_sync(0xffffffffu, sn, o);
        }
        if (lane == 0){
            int gr = bh*2048 + it*64 + row;
            g_thr[gr] = __expf(-ss);
            g_Ea[gr]  = __expf(ss);
            g_Eb[gr]  = __expf(0.2f*ss);
            g_Fa[gr]  = __expf(sn);
            g_Fb[gr]  = __expf(0.2f*sn);
        }
    }

    // ---- fragment pack: two jc tiles (rows 0-31, 32-63) ----
    u32* dst = g_fB + ((size_t)bh*64 + it*2)*2048;
    #pragma unroll
    for (int q = 0; q < 8; q++){
        int e = q*256 + t;                       // 0..2047
        int tile = e >> 10, ee = e & 1023;
        int ks = ee >> 9, nt = (ee >> 6) & 7, ln = (ee >> 1) & 31, r = ee & 1;
        int g2 = ln >> 2, tt2 = ln & 3;
        int jl = tile*32 + ks*16 + r*8 + 2*tt2;
        int n  = nt*8 + g2;
        float v0 = Xs[jl*64 + n];
        float v1 = Xs[(jl + 1)*64 + n];
        u32 hi, lo; split2(v0, v1, hi, lo);
        dst[(size_t)tile*2048 + ee]        = hi;
        dst[(size_t)tile*2048 + 1024 + ee] = lo;
    }
}

// ================= kernel 2: mask nonzero scan (DRAM-bound) =================
// grid 4096 x 256; 16M floats, 4 uint4 per thread
__global__ void __launch_bounds__(256) k_mchk(const float* __restrict__ mask){
    const uint4* m4 = (const uint4*)mask;
    size_t q = (size_t)blockIdx.x*256 + threadIdx.x;
    uint4 a = m4[q];
    uint4 b = m4[q + 1048576];
    uint4 c = m4[q + 2097152];
    uint4 d = m4[q + 3145728];
    u32 v = a.x|a.y|a.z|a.w | b.x|b.y|b.z|b.w | c.x|c.y|c.z|c.w | d.x|d.y|d.z|d.w;
    if (__any_sync(0xffffffffu, v != 0u))
        if ((threadIdx.x & 31) == 0) atomicOr(&g_mflag, 1);
}

// ================= kernel 3: unnormalized P -> mma.sync GEMM + per-row Z/S partials =================
// grid (64,4,4): x = js*16+it, y=h, z=b; 256 threads = 8 warps, warp w rows [16w,16w+16)
__global__ void __launch_bounds__(256, 2) k_main(const float* __restrict__ adj,
                                                 const float* __restrict__ mask){
    __shared__ __align__(16) u32 BfS[2][2048];
    __shared__ float FaS[512], FbS[512];
    __shared__ int   rD[256], rA[256];

    int b = blockIdx.z, h = blockIdx.y;
    int js = blockIdx.x >> 4, it = blockIdx.x & 15;
    int t = threadIdx.x, wid = t >> 5, lane = t & 31;
    int g = lane >> 2, tt = lane & 3;
    int bh = b*4 + h;

    for (int e = t; e < 512; e += 256){
        FaS[e] = g_Fa[bh*2048 + js*512 + e];
        FbS[e] = g_Fb[bh*2048 + js*512 + e];
    }

    int r0 = it*128 + wid*16 + g;
    float thr0 = g_thr[bh*2048 + r0], thr1 = g_thr[bh*2048 + r0 + 8];
    float Ea0  = g_Ea [bh*2048 + r0], Ea1  = g_Ea [bh*2048 + r0 + 8];
    float Eb0  = g_Eb [bh*2048 + r0], Eb1  = g_Eb [bh*2048 + r0 + 8];
    size_t row0 = ((size_t)(b*2048 + r0))*2048 + js*512;
    size_t row1 = row0 + (size_t)8*2048;
    const bool mz = (g_mflag == 0);

    const u32* fBsrc = g_fB + ((size_t)bh*64 + js*16)*2048;

    float acc[8][4];
    #pragma unroll
    for (int nt = 0; nt < 8; nt++)
        #pragma unroll
        for (int r = 0; r < 4; r++) acc[nt][r] = 0.f;

    float zp0 = 0.f, zp1 = 0.f, sp0 = 0.f, sp1 = 0.f;
    int cntD = 0, cntA = 0;

    #define STAGE_B(c) do { \
        const uint4* _s = (const uint4*)(fBsrc + (size_t)(c)*2048); \
        uint4* _d = (uint4*)BfS[(c) & 1]; \
        _d[t] = _s[t]; _d[t + 256] = _s[t + 256]; \
    } while(0)

    #define PHASE_A(c, AH, AL) do { \
        int _cb = (c)*32; \
        _Pragma("unroll") \
        for (int _ks = 0; _ks < 2; _ks++){ \
            _Pragma("unroll") \
            for (int _q = 0; _q < 2; _q++){ \
                int _col = _cb + _ks*16 + _q*8 + 2*tt; \
                float2 _a0 = *(const float2*)(adj + row0 + _col); \
                float2 _a1 = *(const float2*)(adj + row1 + _col); \
                float2 _fa = *(const float2*)(FaS + _col); \
                float2 _fb = *(const float2*)(FbS + _col); \
                float _w00 = (_fa.x > thr0) ? Ea0*_fa.x : Eb0*_fb.x; \
                float _w01 = (_fa.y > thr0) ? Ea0*_fa.y : Eb0*_fb.y; \
                float _w10 = (_fa.x > thr1) ? Ea1*_fa.x : Eb1*_fb.x; \
                float _w11 = (_fa.y > thr1) ? Ea1*_fa.y : Eb1*_fb.y; \
                if (!mz){ \
                    _w00 *= __expf(mask[row0 + _col]);  _w01 *= __expf(mask[row0 + _col + 1]); \
                    _w10 *= __expf(mask[row1 + _col]);  _w11 *= __expf(mask[row1 + _col + 1]); \
                } \
                float _p00 = _a0.x*_w00, _p01 = _a0.y*_w01; \
                float _p10 = _a1.x*_w10, _p11 = _a1.y*_w11; \
                zp0 += _w00 + _w01;  zp1 += _w10 + _w11; \
                sp0 += fabsf(_p00) + fabsf(_p01); \
                sp1 += fabsf(_p10) + fabsf(_p11); \
                cntD += (_p00 != 0.f) + (_p01 != 0.f) + (_p10 != 0.f) + (_p11 != 0.f); \
                cntA += (_a0.x != 0.f) + (_a0.y != 0.f) + (_a1.x != 0.f) + (_a1.y != 0.f); \
                split2(_p00, _p01, AH[_ks*4 + _q*2],     AL[_ks*4 + _q*2]); \
                split2(_p10, _p11, AH[_ks*4 + _q*2 + 1], AL[_ks*4 + _q*2 + 1]); \
            } \
        } \
    } while(0)

    #define MMA_CHUNK(c, AH, AL) do { \
        const u32* _B = BfS[(c) & 1]; \
        _Pragma("unroll") \
        for (int _ks = 0; _ks < 2; _ks++){ \
            _Pragma("unroll") \
            for (int _nt = 0; _nt < 8; _nt++){ \
                int _ix = (_ks*8 + _nt)*64 + lane*2; \
                u64 _bhp = *(const u64*)&_B[_ix]; \
                u64 _blp = *(const u64*)&_B[1024 + _ix]; \
                u32 _bh0 = (u32)_bhp, _bh1 = (u32)(_bhp >> 32); \
                u32 _bl0 = (u32)_blp, _bl1 = (u32)(_blp >> 32); \
                mma16816(acc[_nt], &AH[_ks*4], _bh0, _bh1); \
                mma16816(acc[_nt], &AL[_ks*4], _bh0, _bh1); \
                mma16816(acc[_nt], &AH[_ks*4], _bl0, _bl1); \
            } \
        } \
    } while(0)

    u32 ahA[8], alA[8], ahB[8], alB[8];

    STAGE_B(0);
    __syncthreads();
    PHASE_A(0, ahA, alA);

    #pragma unroll 1
    for (int c = 0; c < 16; c += 2){
        STAGE_B(c + 1);
        PHASE_A(c + 1, ahB, alB);
        MMA_CHUNK(c, ahA, alA);
        __syncthreads();
        if (c + 2 < 16){
            STAGE_B(c + 2);
            PHASE_A(c + 2, ahA, alA);
        }
        MMA_CHUNK(c + 1, ahB, alB);
        __syncthreads();
    }

    // ---- per-row Z / S partials: reduce over tt quad, write by tt==0 lane ----
    #pragma unroll
    for (int o = 1; o <= 2; o <<= 1){
        zp0 += __shfl_xor_sync(0xffffffffu, zp0, o);
        zp1 += __shfl_xor_sync(0xffffffffu, zp1, o);
        sp0 += __shfl_xor_sync(0xffffffffu, sp0, o);
        sp1 += __shfl_xor_sync(0xffffffffu, sp1, o);
    }
    if (tt == 0){
        int zi = js*32768 + bh*2048 + r0;
        g_zpart[zi]     = zp0;  g_zpart[zi + 8] = zp1;
        g_spart[zi]     = sp0;  g_spart[zi + 8] = sp1;
    }

    // ---- epilogue: write unnormalized partial tile ----
    {
        float* po = g_part + (size_t)js*OUTEL;
        size_t base = ((size_t)(b*2048 + r0))*256 + h*64 + 2*tt;
        #pragma unroll
        for (int nt = 0; nt < 8; nt++){
            *(float2*)&po[base + nt*8]         = make_float2(acc[nt][0], acc[nt][1]);
            *(float2*)&po[base + nt*8 + 8*256] = make_float2(acc[nt][2], acc[nt][3]);
        }
    }

    // ---- deterministic count reduce ----
    rD[t] = cntD; rA[t] = cntA;
    __syncthreads();
    #pragma unroll
    for (int s = 128; s > 0; s >>= 1){
        if (t < s){ rD[t] += rD[t + s]; rA[t] += rA[t + s]; }
        __syncthreads();
    }
    if (t == 0){
        int pb = ((bh*16 + it)*4) + js;
        g_pcd[pb] = rD[0]; g_pca[pb] = rA[0];
    }
    #undef STAGE_B
    #undef PHASE_A
    #undef MMA_CHUNK
}

// ================= kernel 4: combine partials, normalize, bias + BN + relu =================
__global__ void __launch_bounds__(256) k_epi(const float* __restrict__ bias,
                                             float* __restrict__ out){
    const float SC = 0.9995003746877732f;   // 1/sqrt(1.001)
    int idx = blockIdx.x*256 + threadIdx.x;
    int hk = (idx*4) & 255;
    int r = idx >> 6;                        // b*2048 + n
    int h = (idx >> 4) & 3;
    int zi = ((r >> 11)*4 + h)*2048 + (r & 2047);
    float Z = g_zpart[zi] + g_zpart[zi + 32768] + g_zpart[zi + 65536] + g_zpart[zi + 98304];
    float iz = 1.f / Z;
    const float4* p = (const float4*)g_part;
    float4 s0 = p[idx];
    float4 s1 = p[idx +   OUTEL/4];
    float4 s2 = p[idx + 2*OUTEL/4];
    float4 s3 = p[idx + 3*OUTEL/4];
    float4 bi = *(const float4*)&bias[hk];
    float4 o;
    o.x = fmaxf(((s0.x + s1.x + s2.x + s3.x)*iz + bi.x)*SC, 0.f);
    o.y = fmaxf(((s0.y + s1.y + s2.y + s3.y)*iz + bi.y)*SC, 0.f);
    o.z = fmaxf(((s0.z + s1.z + s2.z + s3.z)*iz + bi.z)*SC, 0.f);
    o.w = fmaxf(((s0.w + s1.w + s2.w + s3.w)*iz + bi.w)*SC, 0.f);
    ((float4*)out)[idx] = o;
}

// ================= kernel 5a: per-(bh) e_loss row sums (deterministic) =================
__global__ void __launch_bounds__(256) k_loss1(){
    __shared__ float rs[256];
    int bh = blockIdx.x, t = threadIdx.x;
    float se = 0.f;
    #pragma unroll
    for (int k = 0; k < 8; k++){
        int zi = bh*2048 + t + k*256;
        float Z = g_zpart[zi] + g_zpart[zi + 32768] + g_zpart[zi + 65536] + g_zpart[zi + 98304];
        float S = g_spart[zi] + g_spart[zi + 32768] + g_spart[zi + 65536] + g_spart[zi + 98304];
        se += S / Z;
    }
    rs[t] = se;
    __syncthreads();
    #pragma unroll
    for (int s = 128; s > 0; s >>= 1){
        if (t < s) rs[t] += rs[t + s];
        __syncthreads();
    }
    if (t == 0) g_lsum[bh] = rs[0];
}

// ================= kernel 5b: finalize aux losses =================
__global__ void k_loss2(float* __restrict__ out){
    int b = threadIdx.x;
    if (b < 4){
        int d = 0, a = 0;
        for (int p = 0; p < 256; p++){
            int idx = b*256 + p;
            d += g_pcd[idx]; a += g_pca[idx];
        }
        float e = g_lsum[b*4] + g_lsum[b*4+1] + g_lsum[b*4+2] + g_lsum[b*4+3];
        out[OUTEL + b]     = (float)(d - a) * (1.f/2048.f);
        out[OUTEL + 4 + b] = e * (1.f/2048.f);
    }
}

// ================= launch =================
extern "C" void kernel_launch(void* const* d_in, const int* in_sizes, int n_in,
                              void* d_out, int out_size){
    const float* x       = (const float*)d_in[0];
    const float* adj     = (const float*)d_in[1];
    const float* mask    = (const float*)d_in[2];
    const float* W       = (const float*)d_in[3];
    const float* a_self  = (const float*)d_in[4];
    const float* a_neigh = (const float*)d_in[5];
    const float* bias    = (const float*)d_in[6];
    float* out = (float*)d_out;

    k_feats <<<dim3(32, 4, 4), 256>>>(x, W, a_self, a_neigh);
    k_mchk  <<<4096, 256>>>(mask);
    k_main  <<<dim3(64, 4, 4), 256>>>(adj, mask);
    k_epi   <<<2048, 256>>>(bias, out);
    k_loss1 <<<16, 256>>>();
    k_loss2 <<<1, 32>>>(out);
}

// round 12
// speedup vs baseline: 1.7029x; 1.2454x over previous
#include <cuda_runtime.h>
#include <cuda_fp16.h>
#include <math.h>
#include <stdint.h>

typedef unsigned long long u64;
typedef unsigned int u32;
#define DINL __device__ __forceinline__

#define OUTEL  2097152            // 4*2048*256

// ---------------- scratch ----------------
static __device__ float g_Fa [32768];             // e^{sn}
static __device__ float g_Fb [32768];             // e^{0.2 sn}
static __device__ float g_thr[32768];             // e^{-ss}
static __device__ float g_Ea [32768];             // e^{ss}
static __device__ float g_Eb [32768];             // e^{0.2 ss}
static __device__ float g_epart[256];             // per-block e_loss partials
static __device__ int   g_pcd[256];
static __device__ int   g_pca[256];
static __device__ int   g_mflag;
// B fragments: [bh][jc=64][512 uint4]  {hi_r0, hi_r1, lo_r0, lo_r1}
static __device__ uint4 g_fB4[16*64*512];

// ---------------- mma.sync m16n8k16 fp16 (arch-neutral PTX) ----------------
DINL void mma16816(float* d, const u32* a, u32 b0, u32 b1){
    asm volatile(
        "mma.sync.aligned.m16n8k16.row.col.f32.f16.f16.f32 "
        "{%0,%1,%2,%3}, {%4,%5,%6,%7}, {%8,%9}, {%0,%1,%2,%3};"
        : "+f"(d[0]), "+f"(d[1]), "+f"(d[2]), "+f"(d[3])
        : "r"(a[0]), "r"(a[1]), "r"(a[2]), "r"(a[3]), "r"(b0), "r"(b1));
}
DINL u32 pk_h2(float p0, float p1){
    __half2 hh = __floats2half2_rn(p0, p1);
    return *(u32*)&hh;
}
DINL void splitF(float v0, float v1, u32& hi, u32& lo){
    __half2 hh = __floats2half2_rn(v0, v1);
    float2 bk = __half22float2(hh);
    __half2 ll = __floats2half2_rn(v0 - bk.x, v1 - bk.y);
    hi = *(u32*)&hh; lo = *(u32*)&ll;
}

// ================= kernel 1: feats GEMM + scores + fp16 fragment pack (fused) =================
// grid (32, 4, 4) = (ntile64, h, b), 256 threads
__global__ void __launch_bounds__(256) k_feats(const float* __restrict__ x,
                                               const float* __restrict__ W,
                                               const float* __restrict__ a_self,
                                               const float* __restrict__ a_neigh){
    __shared__ float Ws[4096];
    __shared__ float Xs[64*65];          // pad 65 vs bank conflicts in pack phase
    int b = blockIdx.z, h = blockIdx.y, it = blockIdx.x, t = threadIdx.x;
    int bh = b*4 + h;
    if (b == 0 && h == 0 && it == 0 && t == 0) g_mflag = 0;
    const float* wsrc = W + h*4096;
    const float* xsrc = x + (b*2048 + it*64)*64;
    for (int e = t; e < 4096; e += 256){
        Ws[e] = wsrc[e];
        Xs[(e >> 6)*65 + (e & 63)] = xsrc[e];
    }
    __syncthreads();
    int k = t & 63, rg = t >> 6;
    float acc[16];
    #pragma unroll
    for (int r = 0; r < 16; r++) acc[r] = 0.f;
    #pragma unroll 8
    for (int f = 0; f < 64; f++){
        float wf = Ws[f*64 + k];
        #pragma unroll
        for (int r = 0; r < 16; r++) acc[r] += Xs[(rg*16 + r)*65 + f] * wf;
    }
    __syncthreads();
    #pragma unroll
    for (int r = 0; r < 16; r++) Xs[(rg*16 + r)*65 + k] = acc[r];   // feats tile
    __syncthreads();

    // ---- scores: warp wid handles rows wid*8..+7 ----
    int wid = t >> 5, lane = t & 31;
    float as0 = a_self[h*64 + lane],  as1 = a_self[h*64 + lane + 32];
    float an0 = a_neigh[h*64 + lane], an1 = a_neigh[h*64 + lane + 32];
    #pragma unroll
    for (int rr = 0; rr < 8; rr++){
        int row = wid*8 + rr;
        float f0 = Xs[row*65 + lane], f1 = Xs[row*65 + lane + 32];
        float ss = f0*as0 + f1*as1;
        float sn = f0*an0 + f1*an1;
        #pragma unroll
        for (int o = 16; o > 0; o >>= 1){
            ss += __shfl_xor_sync(0xffffffffu, ss, o);
            sn += __shfl_xor_sync(0xffffffffu, sn, o);
        }
        if (lane == 0){
            int gr = bh*2048 + it*64 + row;
            g_thr[gr] = __expf(-ss);
            g_Ea[gr]  = __expf(ss);
            g_Eb[gr]  = __expf(0.2f*ss);
            g_Fa[gr]  = __expf(sn);
            g_Fb[gr]  = __expf(0.2f*sn);
        }
    }

    // ---- fp16 hi/lo interleaved fragment pack: two jc tiles ----
    uint4* dst = g_fB4 + ((size_t)bh*64 + it*2)*512;
    #pragma unroll
    for (int q = 0; q < 4; q++){
        int e = q*256 + t;                       // 0..1023
        int tile = e >> 9, ee = e & 511;
        int ks = ee >> 8, nt = (ee >> 5) & 7, ln = ee & 31;
        int g2 = ln >> 2, tt2 = ln & 3;
        int n  = nt*8 + g2;
        int j0 = tile*32 + ks*16 + 2*tt2;        // r=0 row
        u32 hi0, lo0, hi1, lo1;
        splitF(Xs[j0*65 + n],       Xs[(j0+1)*65 + n], hi0, lo0);
        splitF(Xs[(j0+8)*65 + n],   Xs[(j0+9)*65 + n], hi1, lo1);
        dst[(size_t)tile*512 + (ks*8 + nt)*32 + ln] = make_uint4(hi0, hi1, lo0, lo1);
    }
}

// ================= kernel 2: mask nonzero scan (DRAM-bound) =================
__global__ void __launch_bounds__(256) k_mchk(const float* __restrict__ mask){
    const uint4* m4 = (const uint4*)mask;
    size_t q = (size_t)blockIdx.x*256 + threadIdx.x;
    uint4 a = m4[q];
    uint4 b = m4[q + 1048576];
    uint4 c = m4[q + 2097152];
    uint4 d = m4[q + 3145728];
    u32 v = a.x|a.y|a.z|a.w | b.x|b.y|b.z|b.w | c.x|c.y|c.z|c.w | d.x|d.y|d.z|d.w;
    if (__any_sync(0xffffffffu, v != 0u))
        if ((threadIdx.x & 31) == 0) atomicOr(&g_mflag, 1);
}

// ================= kernel 3: full-row fused attention GEMM =================
// grid (16,4,4): x=it (128-row tile), y=h, z=b; 256 threads = 8 warps; ONE wave on chip.
// Each block covers all 2048 j's -> owns full Z -> writes normalized final output.
__global__ void __launch_bounds__(256, 2) k_main(const float* __restrict__ adj,
                                                 const float* __restrict__ mask,
                                                 const float* __restrict__ bias,
                                                 float* __restrict__ out){
    __shared__ __align__(16) uint4 BfS[2][512];   // double-buffered B tiles (16KB)
    __shared__ float FaS[2048], FbS[2048];        // 16KB
    __shared__ float rE[8];
    __shared__ int   rD[256], rA[256];

    int b = blockIdx.z, h = blockIdx.y, it = blockIdx.x;
    int t = threadIdx.x, wid = t >> 5, lane = t & 31;
    int g = lane >> 2, tt = lane & 3;
    int bh = b*4 + h;

    for (int e = t; e < 2048; e += 256){
        FaS[e] = g_Fa[bh*2048 + e];
        FbS[e] = g_Fb[bh*2048 + e];
    }

    int r0 = it*128 + wid*16 + g;
    float thr0 = g_thr[bh*2048 + r0], thr1 = g_thr[bh*2048 + r0 + 8];
    float Ea0  = g_Ea [bh*2048 + r0], Ea1  = g_Ea [bh*2048 + r0 + 8];
    float Eb0  = g_Eb [bh*2048 + r0], Eb1  = g_Eb [bh*2048 + r0 + 8];
    size_t row0 = ((size_t)(b*2048 + r0))*2048;
    size_t row1 = row0 + (size_t)8*2048;
    const bool mz = (g_mflag == 0);

    const uint4* fB = g_fB4 + (size_t)bh*64*512;

    float acc[8][4];
    #pragma unroll
    for (int nt = 0; nt < 8; nt++)
        #pragma unroll
        for (int r = 0; r < 4; r++) acc[nt][r] = 0.f;

    float zp0 = 0.f, zp1 = 0.f, sp0 = 0.f, sp1 = 0.f;
    int cntD = 0, cntA = 0;

    #define STAGE_B(c) do { \
        const uint4* _s = fB + (size_t)(c)*512; \
        uint4* _d = BfS[(c) & 1]; \
        _d[t] = _s[t]; _d[t + 256] = _s[t + 256]; \
    } while(0)

    #define PHASE_A(c, AH) do { \
        int _cb = (c)*32; \
        _Pragma("unroll") \
        for (int _ks = 0; _ks < 2; _ks++){ \
            _Pragma("unroll") \
            for (int _q = 0; _q < 2; _q++){ \
                int _col = _cb + _ks*16 + _q*8 + 2*tt; \
                float2 _a0 = *(const float2*)(adj + row0 + _col); \
                float2 _a1 = *(const float2*)(adj + row1 + _col); \
                float2 _fa = *(const float2*)(FaS + _col); \
                float2 _fb = *(const float2*)(FbS + _col); \
                float _w00 = (_fa.x > thr0) ? Ea0*_fa.x : Eb0*_fb.x; \
                float _w01 = (_fa.y > thr0) ? Ea0*_fa.y : Eb0*_fb.y; \
                float _w10 = (_fa.x > thr1) ? Ea1*_fa.x : Eb1*_fb.x; \
                float _w11 = (_fa.y > thr1) ? Ea1*_fa.y : Eb1*_fb.y; \
                if (!mz){ \
                    _w00 *= __expf(mask[row0 + _col]);  _w01 *= __expf(mask[row0 + _col + 1]); \
                    _w10 *= __expf(mask[row1 + _col]);  _w11 *= __expf(mask[row1 + _col + 1]); \
                } \
                float _p00 = _a0.x*_w00, _p01 = _a0.y*_w01; \
                float _p10 = _a1.x*_w10, _p11 = _a1.y*_w11; \
                zp0 += _w00 + _w01;  zp1 += _w10 + _w11; \
                sp0 += fabsf(_p00) + fabsf(_p01); \
                sp1 += fabsf(_p10) + fabsf(_p11); \
                cntD += (_p00 != 0.f) + (_p01 != 0.f) + (_p10 != 0.f) + (_p11 != 0.f); \
                cntA += (_a0.x != 0.f) + (_a0.y != 0.f) + (_a1.x != 0.f) + (_a1.y != 0.f); \
                AH[_ks*4 + _q*2]     = pk_h2(_p00, _p01); \
                AH[_ks*4 + _q*2 + 1] = pk_h2(_p10, _p11); \
            } \
        } \
    } while(0)

    #define MMA_CHUNK(c, AH) do { \
        const uint4* _B = BfS[(c) & 1]; \
        _Pragma("unroll") \
        for (int _ks = 0; _ks < 2; _ks++){ \
            _Pragma("unroll") \
            for (int _nt = 0; _nt < 8; _nt++){ \
                uint4 _bb = _B[(_ks*8 + _nt)*32 + lane]; \
                mma16816(acc[_nt], &AH[_ks*4], _bb.x, _bb.y); \
                mma16816(acc[_nt], &AH[_ks*4], _bb.z, _bb.w); \
            } \
        } \
    } while(0)

    u32 ahA[8], ahB[8];

    STAGE_B(0);
    __syncthreads();
    PHASE_A(0, ahA);

    #pragma unroll 1
    for (int c = 0; c < 64; c += 2){
        STAGE_B(c + 1);
        PHASE_A(c + 1, ahB);
        MMA_CHUNK(c, ahA);
        __syncthreads();
        if (c + 2 < 64){
            STAGE_B(c + 2);
            PHASE_A(c + 2, ahA);
        }
        MMA_CHUNK(c + 1, ahB);
        __syncthreads();
    }

    // ---- full-row Z and S via quad reduce (tt) ----
    #pragma unroll
    for (int o = 1; o <= 2; o <<= 1){
        zp0 += __shfl_xor_sync(0xffffffffu, zp0, o);
        zp1 += __shfl_xor_sync(0xffffffffu, zp1, o);
        sp0 += __shfl_xor_sync(0xffffffffu, sp0, o);
        sp1 += __shfl_xor_sync(0xffffffffu, sp1, o);
    }
    float iz0 = 1.f / zp0, iz1 = 1.f / zp1;

    // ---- e_loss warp partial (each quad lane holds same value; scale by 1/4) ----
    float eterm = (sp0*iz0 + sp1*iz1) * 0.25f;
    #pragma unroll
    for (int o = 16; o > 0; o >>= 1) eterm += __shfl_xor_sync(0xffffffffu, eterm, o);
    if (lane == 0) rE[wid] = eterm;

    // ---- epilogue: normalize + bias + BN + relu, write final out ----
    const float SC = 0.9995003746877732f;   // 1/sqrt(1.001)
    size_t obase = ((size_t)(b*2048 + r0))*256 + h*64 + 2*tt;
    #pragma unroll
    for (int nt = 0; nt < 8; nt++){
        float2 bi = *(const float2*)&bias[h*64 + nt*8 + 2*tt];
        float2 o0, o1;
        o0.x = fmaxf((acc[nt][0]*iz0 + bi.x)*SC, 0.f);
        o0.y = fmaxf((acc[nt][1]*iz0 + bi.y)*SC, 0.f);
        o1.x = fmaxf((acc[nt][2]*iz1 + bi.x)*SC, 0.f);
        o1.y = fmaxf((acc[nt][3]*iz1 + bi.y)*SC, 0.f);
        *(float2*)&out[obase + nt*8]         = o0;
        *(float2*)&out[obase + nt*8 + 8*256] = o1;
    }

    // ---- deterministic block reduces ----
    rD[t] = cntD; rA[t] = cntA;
    __syncthreads();
    #pragma unroll
    for (int s = 128; s > 0; s >>= 1){
        if (t < s){ rD[t] += rD[t + s]; rA[t] += rA[t + s]; }
        __syncthreads();
    }
    if (t == 0){
        int pb = bh*16 + it;
        g_pcd[pb] = rD[0]; g_pca[pb] = rA[0];
        float e = 0.f;
        #pragma unroll
        for (int w = 0; w < 8; w++) e += rE[w];
        g_epart[pb] = e;
    }
    #undef STAGE_B
    #undef PHASE_A
    #undef MMA_CHUNK
}

// ================= kernel 4: finalize aux losses =================
__global__ void k_loss(float* __restrict__ out){
    int b = threadIdx.x;
    if (b < 4){
        int d = 0, a = 0; float e = 0.f;
        for (int p = 0; p < 64; p++){
            int idx = b*64 + p;
            d += g_pcd[idx]; a += g_pca[idx]; e += g_epart[idx];
        }
        out[OUTEL + b]     = (float)(d - a) * (1.f/2048.f);
        out[OUTEL + 4 + b] = e * (1.f/2048.f);
    }
}

// ================= launch =================
extern "C" void kernel_launch(void* const* d_in, const int* in_sizes, int n_in,
                              void* d_out, int out_size){
    const float* x       = (const float*)d_in[0];
    const float* adj     = (const float*)d_in[1];
    const float* mask    = (const float*)d_in[2];
    const float* W       = (const float*)d_in[3];
    const float* a_self  = (const float*)d_in[4];
    const float* a_neigh = (const float*)d_in[5];
    const float* bias    = (const float*)d_in[6];
    float* out = (float*)d_out;

    k_feats <<<dim3(32, 4, 4), 256>>>(x, W, a_self, a_neigh);
    k_mchk  <<<4096, 256>>>(mask);
    k_main  <<<dim3(16, 4, 4), 256>>>(adj, mask, bias, out);
    k_loss  <<<1, 32>>>(out);
}

// round 13
// speedup vs baseline: 1.7835x; 1.0473x over previous
#include <cuda_runtime.h>
#include <cuda_fp16.h>
#include <math.h>
#include <stdint.h>

typedef unsigned long long u64;
typedef unsigned int u32;
#define DINL __device__ __forceinline__

#define OUTEL  2097152            // 4*2048*256

// ---------------- scratch ----------------
static __device__ float g_Fa [32768];             // e^{sn}
static __device__ float g_Fb [32768];             // e^{0.2 sn}
static __device__ float g_thr[32768];             // e^{-ss}
static __device__ float g_Ea [32768];             // e^{ss}
static __device__ float g_Eb [32768];             // e^{0.2 ss}
static __device__ float g_epart[256];             // per-block e_loss partials
static __device__ int   g_pcd[256];
static __device__ int   g_pca[256];
static __device__ int   g_mpart[512];             // per-k_feats-block mask-nonzero flag
static __device__ int   g_tick;                   // completion ticket for k_main
// B fragments: [bh][jc=64][512 uint4]  {hi_r0, hi_r1, lo_r0, lo_r1}
static __device__ uint4 g_fB4[16*64*512];

// ---------------- mma.sync m16n8k16 fp16 (arch-neutral PTX) ----------------
DINL void mma16816(float* d, const u32* a, u32 b0, u32 b1){
    asm volatile(
        "mma.sync.aligned.m16n8k16.row.col.f32.f16.f16.f32 "
        "{%0,%1,%2,%3}, {%4,%5,%6,%7}, {%8,%9}, {%0,%1,%2,%3};"
        : "+f"(d[0]), "+f"(d[1]), "+f"(d[2]), "+f"(d[3])
        : "r"(a[0]), "r"(a[1]), "r"(a[2]), "r"(a[3]), "r"(b0), "r"(b1));
}
DINL u32 pk_h2(float p0, float p1){
    __half2 hh = __floats2half2_rn(p0, p1);
    return *(u32*)&hh;
}
DINL void splitF(float v0, float v1, u32& hi, u32& lo){
    __half2 hh = __floats2half2_rn(v0, v1);
    float2 bk = __half22float2(hh);
    __half2 ll = __floats2half2_rn(v0 - bk.x, v1 - bk.y);
    hi = *(u32*)&hh; lo = *(u32*)&ll;
}

// ================= kernel 1: feats GEMM + scores + fp16 pack + mask scan (all fused) =================
// grid (32, 4, 4) = (ntile64, h, b), 256 threads
__global__ void __launch_bounds__(256) k_feats(const float* __restrict__ x,
                                               const float* __restrict__ W,
                                               const float* __restrict__ a_self,
                                               const float* __restrict__ a_neigh,
                                               const float* __restrict__ mask){
    __shared__ float Ws[4096];
    __shared__ float Xs[64*65];          // pad 65 vs bank conflicts in pack phase
    int b = blockIdx.z, h = blockIdx.y, it = blockIdx.x, t = threadIdx.x;
    int bh = b*4 + h;
    int L = bh*32 + it;                  // linear block id 0..511
    if (L == 0 && t == 0) g_tick = 0;    // reset completion ticket for this launch
    const float* wsrc = W + h*4096;
    const float* xsrc = x + (b*2048 + it*64)*64;
    for (int e = t; e < 4096; e += 256){
        Ws[e] = wsrc[e];
        Xs[(e >> 6)*65 + (e & 63)] = xsrc[e];
    }
    __syncthreads();
    int k = t & 63, rg = t >> 6;
    float acc[16];
    #pragma unroll
    for (int r = 0; r < 16; r++) acc[r] = 0.f;
    #pragma unroll 8
    for (int f = 0; f < 64; f++){
        float wf = Ws[f*64 + k];
        #pragma unroll
        for (int r = 0; r < 16; r++) acc[r] += Xs[(rg*16 + r)*65 + f] * wf;
    }
    __syncthreads();
    #pragma unroll
    for (int r = 0; r < 16; r++) Xs[(rg*16 + r)*65 + k] = acc[r];   // feats tile
    __syncthreads();

    // ---- scores: warp wid handles rows wid*8..+7 ----
    int wid = t >> 5, lane = t & 31;
    float as0 = a_self[h*64 + lane],  as1 = a_self[h*64 + lane + 32];
    float an0 = a_neigh[h*64 + lane], an1 = a_neigh[h*64 + lane + 32];
    #pragma unroll
    for (int rr = 0; rr < 8; rr++){
        int row = wid*8 + rr;
        float f0 = Xs[row*65 + lane], f1 = Xs[row*65 + lane + 32];
        float ss = f0*as0 + f1*as1;
        float sn = f0*an0 + f1*an1;
        #pragma unroll
        for (int o = 16; o > 0; o >>= 1){
            ss += __shfl_xor_sync(0xffffffffu, ss, o);
            sn += __shfl_xor_sync(0xffffffffu, sn, o);
        }
        if (lane == 0){
            int gr = bh*2048 + it*64 + row;
            g_thr[gr] = __expf(-ss);
            g_Ea[gr]  = __expf(ss);
            g_Eb[gr]  = __expf(0.2f*ss);
            g_Fa[gr]  = __expf(sn);
            g_Fb[gr]  = __expf(0.2f*sn);
        }
    }

    // ---- fp16 hi/lo interleaved fragment pack: two jc tiles ----
    uint4* dst = g_fB4 + ((size_t)bh*64 + it*2)*512;
    #pragma unroll
    for (int q = 0; q < 4; q++){
        int e = q*256 + t;                       // 0..1023
        int tile = e >> 9, ee = e & 511;
        int ks = ee >> 8, nt = (ee >> 5) & 7, ln = ee & 31;
        int g2 = ln >> 2, tt2 = ln & 3;
        int n  = nt*8 + g2;
        int j0 = tile*32 + ks*16 + 2*tt2;        // r=0 row
        u32 hi0, lo0, hi1, lo1;
        splitF(Xs[j0*65 + n],       Xs[(j0+1)*65 + n], hi0, lo0);
        splitF(Xs[(j0+8)*65 + n],   Xs[(j0+9)*65 + n], hi1, lo1);
        dst[(size_t)tile*512 + (ks*8 + nt)*32 + ln] = make_uint4(hi0, hi1, lo0, lo1);
    }

    // ---- mask nonzero scan: 8192 uint4 slice per block ----
    {
        const uint4* m4 = (const uint4*)mask + (size_t)L*8192;
        u32 v = 0;
        #pragma unroll 8
        for (int q = t; q < 8192; q += 256){
            uint4 a = m4[q];
            v |= a.x | a.y | a.z | a.w;
        }
        int any = __syncthreads_or(v != 0u);
        if (t == 0) g_mpart[L] = any;
    }
}

// ================= kernel 2: full-row fused attention GEMM + final losses =================
// grid (16,4,4): x=it (128-row tile), y=h, z=b; 256 threads = 8 warps; ONE wave on chip.
__global__ void __launch_bounds__(256, 2) k_main(const float* __restrict__ adj,
                                                 const float* __restrict__ mask,
                                                 const float* __restrict__ bias,
                                                 float* __restrict__ out){
    __shared__ __align__(16) uint4 BfS[2][512];   // double-buffered B tiles (16KB)
    __shared__ float FaS[2048], FbS[2048];        // 16KB
    __shared__ float rE[8];
    __shared__ float rF[256];
    __shared__ int   rD[256], rA[256];
    __shared__ int   s_last;

    int b = blockIdx.z, h = blockIdx.y, it = blockIdx.x;
    int t = threadIdx.x, wid = t >> 5, lane = t & 31;
    int g = lane >> 2, tt = lane & 3;
    int bh = b*4 + h;

    for (int e = t; e < 2048; e += 256){
        FaS[e] = g_Fa[bh*2048 + e];
        FbS[e] = g_Fb[bh*2048 + e];
    }

    // mask-zero flag: OR of the 512 per-block scan flags
    int mv = g_mpart[t] | g_mpart[t + 256];
    const bool mz = !__syncthreads_or(mv);

    int r0 = it*128 + wid*16 + g;
    float thr0 = g_thr[bh*2048 + r0], thr1 = g_thr[bh*2048 + r0 + 8];
    float Ea0  = g_Ea [bh*2048 + r0], Ea1  = g_Ea [bh*2048 + r0 + 8];
    float Eb0  = g_Eb [bh*2048 + r0], Eb1  = g_Eb [bh*2048 + r0 + 8];
    size_t row0 = ((size_t)(b*2048 + r0))*2048;
    size_t row1 = row0 + (size_t)8*2048;

    const uint4* fB = g_fB4 + (size_t)bh*64*512;

    float acc[8][4];
    #pragma unroll
    for (int nt = 0; nt < 8; nt++)
        #pragma unroll
        for (int r = 0; r < 4; r++) acc[nt][r] = 0.f;

    float zp0 = 0.f, zp1 = 0.f, sp0 = 0.f, sp1 = 0.f;
    int cntD = 0, cntA = 0;

    #define STAGE_B(c) do { \
        const uint4* _s = fB + (size_t)(c)*512; \
        uint4* _d = BfS[(c) & 1]; \
        _d[t] = _s[t]; _d[t + 256] = _s[t + 256]; \
    } while(0)

    // distance-2 adj prefetch into registers
    #define LOAD_A(R, c) do { \
        int _cb = (c)*32 + 2*tt; \
        _Pragma("unroll") \
        for (int _ks = 0; _ks < 2; _ks++){ \
            _Pragma("unroll") \
            for (int _q = 0; _q < 2; _q++){ \
                int _col = _cb + _ks*16 + _q*8; \
                R[_ks*4 + _q*2]     = *(const float2*)(adj + row0 + _col); \
                R[_ks*4 + _q*2 + 1] = *(const float2*)(adj + row1 + _col); \
            } \
        } \
    } while(0)

    #define COMP_A(AH, R, c) do { \
        int _cb = (c)*32 + 2*tt; \
        _Pragma("unroll") \
        for (int _ks = 0; _ks < 2; _ks++){ \
            _Pragma("unroll") \
            for (int _q = 0; _q < 2; _q++){ \
                int _col = _cb + _ks*16 + _q*8; \
                float2 _a0 = R[_ks*4 + _q*2]; \
                float2 _a1 = R[_ks*4 + _q*2 + 1]; \
                float2 _fa = *(const float2*)(FaS + _col); \
                float2 _fb = *(const float2*)(FbS + _col); \
                float _w00 = (_fa.x > thr0) ? Ea0*_fa.x : Eb0*_fb.x; \
                float _w01 = (_fa.y > thr0) ? Ea0*_fa.y : Eb0*_fb.y; \
                float _w10 = (_fa.x > thr1) ? Ea1*_fa.x : Eb1*_fb.x; \
                float _w11 = (_fa.y > thr1) ? Ea1*_fa.y : Eb1*_fb.y; \
                if (!mz){ \
                    _w00 *= __expf(mask[row0 + _col]);  _w01 *= __expf(mask[row0 + _col + 1]); \
                    _w10 *= __expf(mask[row1 + _col]);  _w11 *= __expf(mask[row1 + _col + 1]); \
                } \
                float _p00 = _a0.x*_w00, _p01 = _a0.y*_w01; \
                float _p10 = _a1.x*_w10, _p11 = _a1.y*_w11; \
                zp0 += _w00 + _w01;  zp1 += _w10 + _w11; \
                sp0 += fabsf(_p00) + fabsf(_p01); \
                sp1 += fabsf(_p10) + fabsf(_p11); \
                cntD += (_p00 != 0.f) + (_p01 != 0.f) + (_p10 != 0.f) + (_p11 != 0.f); \
                cntA += (_a0.x != 0.f) + (_a0.y != 0.f) + (_a1.x != 0.f) + (_a1.y != 0.f); \
                AH[_ks*4 + _q*2]     = pk_h2(_p00, _p01); \
                AH[_ks*4 + _q*2 + 1] = pk_h2(_p10, _p11); \
            } \
        } \
    } while(0)

    #define MMA_CHUNK(c, AH) do { \
        const uint4* _B = BfS[(c) & 1]; \
        _Pragma("unroll") \
        for (int _ks = 0; _ks < 2; _ks++){ \
            _Pragma("unroll") \
            for (int _nt = 0; _nt < 8; _nt++){ \
                uint4 _bb = _B[(_ks*8 + _nt)*32 + lane]; \
                mma16816(acc[_nt], &AH[_ks*4], _bb.x, _bb.y); \
                mma16816(acc[_nt], &AH[_ks*4], _bb.z, _bb.w); \
            } \
        } \
    } while(0)

    u32 ahA[8], ahB[8];
    float2 RA[8], RB[8];

    STAGE_B(0);
    LOAD_A(RA, 0);
    __syncthreads();                 // BfS[0] + FaS/FbS ready
    LOAD_A(RB, 1);
    COMP_A(ahA, RA, 0);

    #pragma unroll 1
    for (int c = 0; c < 64; c += 2){
        STAGE_B(c + 1);
        if (c + 2 < 64) LOAD_A(RA, c + 2);
        COMP_A(ahB, RB, c + 1);
        MMA_CHUNK(c, ahA);
        __syncthreads();             // BfS[c+1] staged, BfS[c] free
        if (c + 2 < 64){
            STAGE_B(c + 2);
            if (c + 3 < 64) LOAD_A(RB, c + 3);
            COMP_A(ahA, RA, c + 2);
        }
        MMA_CHUNK(c + 1, ahB);
        __syncthreads();             // BfS[c+2] staged, BfS[c+1] free
    }

    // ---- full-row Z and S via quad reduce (tt) ----
    #pragma unroll
    for (int o = 1; o <= 2; o <<= 1){
        zp0 += __shfl_xor_sync(0xffffffffu, zp0, o);
        zp1 += __shfl_xor_sync(0xffffffffu, zp1, o);
        sp0 += __shfl_xor_sync(0xffffffffu, sp0, o);
        sp1 += __shfl_xor_sync(0xffffffffu, sp1, o);
    }
    float iz0 = 1.f / zp0, iz1 = 1.f / zp1;

    // ---- e_loss warp partial (each quad lane holds same value; scale by 1/4) ----
    float eterm = (sp0*iz0 + sp1*iz1) * 0.25f;
    #pragma unroll
    for (int o = 16; o > 0; o >>= 1) eterm += __shfl_xor_sync(0xffffffffu, eterm, o);
    if (lane == 0) rE[wid] = eterm;

    // ---- epilogue: normalize + bias + BN + relu, write final out ----
    const float SC = 0.9995003746877732f;   // 1/sqrt(1.001)
    size_t obase = ((size_t)(b*2048 + r0))*256 + h*64 + 2*tt;
    #pragma unroll
    for (int nt = 0; nt < 8; nt++){
        float2 bi = *(const float2*)&bias[h*64 + nt*8 + 2*tt];
        float2 o0, o1;
        o0.x = fmaxf((acc[nt][0]*iz0 + bi.x)*SC, 0.f);
        o0.y = fmaxf((acc[nt][1]*iz0 + bi.y)*SC, 0.f);
        o1.x = fmaxf((acc[nt][2]*iz1 + bi.x)*SC, 0.f);
        o1.y = fmaxf((acc[nt][3]*iz1 + bi.y)*SC, 0.f);
        *(float2*)&out[obase + nt*8]         = o0;
        *(float2*)&out[obase + nt*8 + 8*256] = o1;
    }

    // ---- deterministic block reduces ----
    rD[t] = cntD; rA[t] = cntA;
    __syncthreads();
    #pragma unroll
    for (int s = 128; s > 0; s >>= 1){
        if (t < s){ rD[t] += rD[t + s]; rA[t] += rA[t + s]; }
        __syncthreads();
    }
    if (t == 0){
        int pb = bh*16 + it;
        g_pcd[pb] = rD[0]; g_pca[pb] = rA[0];
        float e = 0.f;
        #pragma unroll
        for (int w = 0; w < 8; w++) e += rE[w];
        g_epart[pb] = e;
        __threadfence();
        int r = atomicAdd(&g_tick, 1);
        s_last = (r == 255);
    }
    __syncthreads();

    // ---- last block finalizes the aux losses (deterministic fixed-order reduce) ----
    if (s_last){
        __threadfence();
        rD[t] = g_pcd[t] - g_pca[t];
        rF[t] = g_epart[t];
        __syncthreads();
        #pragma unroll
        for (int s = 32; s > 0; s >>= 1){
            if ((t & 63) < s){ rD[t] += rD[t + s]; rF[t] += rF[t + s]; }
            __syncthreads();
        }
        if ((t & 63) == 0){
            int bb = t >> 6;
            out[OUTEL + bb]     = (float)rD[t] * (1.f/2048.f);
            out[OUTEL + 4 + bb] = rF[t] * (1.f/2048.f);
        }
    }
    #undef STAGE_B
    #undef LOAD_A
    #undef COMP_A
    #undef MMA_CHUNK
}

// ================= launch =================
extern "C" void kernel_launch(void* const* d_in, const int* in_sizes, int n_in,
                              void* d_out, int out_size){
    const float* x       = (const float*)d_in[0];
    const float* adj     = (const float*)d_in[1];
    const float* mask    = (const float*)d_in[2];
    const float* W       = (const float*)d_in[3];
    const float* a_self  = (const float*)d_in[4];
    const float* a_neigh = (const float*)d_in[5];
    const float* bias    = (const float*)d_in[6];
    float* out = (float*)d_out;

    k_feats <<<dim3(32, 4, 4), 256>>>(x, W, a_self, a_neigh, mask);
    k_main  <<<dim3(16, 4, 4), 256>>>(adj, mask, bias, out);
}

// round 14
// speedup vs baseline: 2.3084x; 1.2943x over previous
#include <cuda_runtime.h>
#include <cuda_fp16.h>
#include <math.h>
#include <stdint.h>

typedef unsigned long long u64;
typedef unsigned int u32;
#define DINL __device__ __forceinline__

#define OUTEL  2097152            // 4*2048*256

// ---------------- scratch ----------------
static __device__ float g_Fa [32768];             // e^{sn}
static __device__ float g_Fb [32768];             // e^{0.2 sn}
static __device__ float g_thr[32768];             // e^{-ss}
static __device__ float g_Ea [32768];             // e^{ss}
static __device__ float g_Eb [32768];             // e^{0.2 sn}
static __device__ float g_epart[512];             // per-k_main-block e_loss partials
static __device__ int   g_pcd[512];
static __device__ int   g_pca[512];
static __device__ int   g_mpart[512];             // per-k_feats-block mask-nonzero flag
static __device__ int   g_tick;                   // completion ticket for k_main
// B fragments (single fp16): [bh][jc=64][512 uint2]  entry (ks*8+nt)*32+lane = {b0,b1}
static __device__ uint2 g_fB2[16*64*512];

// ---------------- mma.sync m16n8k16 fp16 (arch-neutral PTX) ----------------
DINL void mma16816(float* d, const u32* a, u32 b0, u32 b1){
    asm volatile(
        "mma.sync.aligned.m16n8k16.row.col.f32.f16.f16.f32 "
        "{%0,%1,%2,%3}, {%4,%5,%6,%7}, {%8,%9}, {%0,%1,%2,%3};"
        : "+f"(d[0]), "+f"(d[1]), "+f"(d[2]), "+f"(d[3])
        : "r"(a[0]), "r"(a[1]), "r"(a[2]), "r"(a[3]), "r"(b0), "r"(b1));
}
DINL u32 pk_h2(float p0, float p1){
    __half2 hh = __floats2half2_rn(p0, p1);
    return *(u32*)&hh;
}

// ================= kernel 1: feats GEMM + scores + fp16 pack + mask scan =================
// grid (32, 4, 4) = (ntile64, h, b), 256 threads
__global__ void __launch_bounds__(256) k_feats(const float* __restrict__ x,
                                               const float* __restrict__ W,
                                               const float* __restrict__ a_self,
                                               const float* __restrict__ a_neigh,
                                               const float* __restrict__ mask){
    __shared__ float Ws[4096];
    __shared__ float Xs[64*65];          // pad 65 vs bank conflicts in pack phase
    int b = blockIdx.z, h = blockIdx.y, it = blockIdx.x, t = threadIdx.x;
    int bh = b*4 + h;
    int L = bh*32 + it;                  // linear block id 0..511
    if (L == 0 && t == 0) g_tick = 0;    // reset completion ticket for this launch
    const float* wsrc = W + h*4096;
    const float* xsrc = x + (b*2048 + it*64)*64;
    for (int e = t; e < 4096; e += 256){
        Ws[e] = wsrc[e];
        Xs[(e >> 6)*65 + (e & 63)] = xsrc[e];
    }
    __syncthreads();
    int k = t & 63, rg = t >> 6;
    float acc[16];
    #pragma unroll
    for (int r = 0; r < 16; r++) acc[r] = 0.f;
    #pragma unroll 8
    for (int f = 0; f < 64; f++){
        float wf = Ws[f*64 + k];
        #pragma unroll
        for (int r = 0; r < 16; r++) acc[r] += Xs[(rg*16 + r)*65 + f] * wf;
    }
    __syncthreads();
    #pragma unroll
    for (int r = 0; r < 16; r++) Xs[(rg*16 + r)*65 + k] = acc[r];   // feats tile
    __syncthreads();

    // ---- scores: warp wid handles rows wid*8..+7 ----
    int wid = t >> 5, lane = t & 31;
    float as0 = a_self[h*64 + lane],  as1 = a_self[h*64 + lane + 32];
    float an0 = a_neigh[h*64 + lane], an1 = a_neigh[h*64 + lane + 32];
    #pragma unroll
    for (int rr = 0; rr < 8; rr++){
        int row = wid*8 + rr;
        float f0 = Xs[row*65 + lane], f1 = Xs[row*65 + lane + 32];
        float ss = f0*as0 + f1*as1;
        float sn = f0*an0 + f1*an1;
        #pragma unroll
        for (int o = 16; o > 0; o >>= 1){
            ss += __shfl_xor_sync(0xffffffffu, ss, o);
            sn += __shfl_xor_sync(0xffffffffu, sn, o);
        }
        if (lane == 0){
            int gr = bh*2048 + it*64 + row;
            g_thr[gr] = __expf(-ss);
            g_Ea[gr]  = __expf(ss);
            g_Eb[gr]  = __expf(0.2f*ss);
            g_Fa[gr]  = __expf(sn);
            g_Fb[gr]  = __expf(0.2f*sn);
        }
    }

    // ---- single-fp16 fragment pack: two jc tiles, 1024 uint2 entries ----
    uint2* dst = g_fB2 + ((size_t)bh*64 + it*2)*512;
    #pragma unroll
    for (int q = 0; q < 4; q++){
        int e = q*256 + t;                       // 0..1023
        int tile = e >> 9, ee = e & 511;
        int ks = ee >> 8, nt = (ee >> 5) & 7, ln = ee & 31;
        int g2 = ln >> 2, tt2 = ln & 3;
        int n  = nt*8 + g2;
        int j0 = tile*32 + ks*16 + 2*tt2;
        u32 b0 = pk_h2(Xs[j0*65 + n],     Xs[(j0+1)*65 + n]);
        u32 b1 = pk_h2(Xs[(j0+8)*65 + n], Xs[(j0+9)*65 + n]);
        dst[(size_t)tile*512 + ee] = make_uint2(b0, b1);
    }

    // ---- mask nonzero scan: 8192 uint4 slice per block ----
    {
        const uint4* m4 = (const uint4*)mask + (size_t)L*8192;
        u32 v = 0;
        #pragma unroll 8
        for (int q = t; q < 8192; q += 256){
            uint4 a = m4[q];
            v |= a.x | a.y | a.z | a.w;
        }
        int any = __syncthreads_or(v != 0u);
        if (t == 0) g_mpart[L] = any;
    }
}

// ================= kernel 2: full-row fused attention GEMM + final losses =================
// grid (32,4,4): x=it (64-row tile), y=h, z=b; 128 threads = 4 warps, warp owns 16 rows.
__global__ void __launch_bounds__(128, 4) k_main(const float* __restrict__ adj,
                                                 const float* __restrict__ mask,
                                                 const float* __restrict__ bias,
                                                 float* __restrict__ out){
    __shared__ __align__(16) uint2 BfS[2][512];   // double-buffered B tiles (8KB)
    __shared__ float FaS[2048], FbS[2048];        // 16KB
    __shared__ float rE[4];
    __shared__ float rF[128];
    __shared__ int   rD[128], rA[128];
    __shared__ int   s_last;

    int b = blockIdx.z, h = blockIdx.y, it = blockIdx.x;
    int t = threadIdx.x, wid = t >> 5, lane = t & 31;
    int g = lane >> 2, tt = lane & 3;
    int bh = b*4 + h;

    {
        const float4* fa4 = (const float4*)(g_Fa + bh*2048);
        const float4* fb4 = (const float4*)(g_Fb + bh*2048);
        #pragma unroll
        for (int q = 0; q < 4; q++){
            ((float4*)FaS)[q*128 + t] = fa4[q*128 + t];
            ((float4*)FbS)[q*128 + t] = fb4[q*128 + t];
        }
    }

    // mask-zero flag: OR of the 512 per-block scan flags
    int mv = g_mpart[t] | g_mpart[t + 128] | g_mpart[t + 256] | g_mpart[t + 384];
    const bool mz = !__syncthreads_or(mv);

    int r0 = it*64 + wid*16 + g;
    float thr0 = g_thr[bh*2048 + r0], thr1 = g_thr[bh*2048 + r0 + 8];
    float Ea0  = g_Ea [bh*2048 + r0], Ea1  = g_Ea [bh*2048 + r0 + 8];
    float Eb0  = g_Eb [bh*2048 + r0], Eb1  = g_Eb [bh*2048 + r0 + 8];
    size_t row0 = ((size_t)(b*2048 + r0))*2048;
    size_t row1 = row0 + (size_t)8*2048;

    const uint4* fB = (const uint4*)(g_fB2 + (size_t)bh*64*512);

    float acc[8][4];
    #pragma unroll
    for (int nt = 0; nt < 8; nt++)
        #pragma unroll
        for (int r = 0; r < 4; r++) acc[nt][r] = 0.f;

    float zp0 = 0.f, zp1 = 0.f, sp0 = 0.f, sp1 = 0.f;
    int cntD = 0, cntA = 0;

    #define STAGE_B(c) do { \
        const uint4* _s = fB + (size_t)(c)*256; \
        uint4* _d = (uint4*)BfS[(c) & 1]; \
        _d[t] = _s[t]; _d[t + 128] = _s[t + 128]; \
    } while(0)

    STAGE_B(0);
    __syncthreads();

    #pragma unroll 1
    for (int c = 0; c < 64; c++){
        if (c + 1 < 64) STAGE_B(c + 1);
        // ---- Phase A: P fragments (regs only) ----
        u32 ah[8];
        #pragma unroll
        for (int ks = 0; ks < 2; ks++){
            #pragma unroll
            for (int q = 0; q < 2; q++){
                int col = c*32 + ks*16 + q*8 + 2*tt;
                float2 a0 = *(const float2*)(adj + row0 + col);
                float2 a1 = *(const float2*)(adj + row1 + col);
                float2 fa = *(const float2*)(FaS + col);
                float2 fb = *(const float2*)(FbS + col);
                float w00 = (fa.x > thr0) ? Ea0*fa.x : Eb0*fb.x;
                float w01 = (fa.y > thr0) ? Ea0*fa.y : Eb0*fb.y;
                float w10 = (fa.x > thr1) ? Ea1*fa.x : Eb1*fb.x;
                float w11 = (fa.y > thr1) ? Ea1*fa.y : Eb1*fb.y;
                if (!mz){
                    w00 *= __expf(mask[row0 + col]);  w01 *= __expf(mask[row0 + col + 1]);
                    w10 *= __expf(mask[row1 + col]);  w11 *= __expf(mask[row1 + col + 1]);
                }
                float p00 = a0.x*w00, p01 = a0.y*w01;
                float p10 = a1.x*w10, p11 = a1.y*w11;
                zp0 += w00 + w01;  zp1 += w10 + w11;
                sp0 += fabsf(p00) + fabsf(p01);
                sp1 += fabsf(p10) + fabsf(p11);
                cntD += (p00 != 0.f) + (p01 != 0.f) + (p10 != 0.f) + (p11 != 0.f);
                cntA += (a0.x != 0.f) + (a0.y != 0.f) + (a1.x != 0.f) + (a1.y != 0.f);
                ah[ks*4 + q*2]     = pk_h2(p00, p01);
                ah[ks*4 + q*2 + 1] = pk_h2(p10, p11);
            }
        }
        // ---- 16 MMAs ----
        const uint2* B = BfS[c & 1];
        #pragma unroll
        for (int ks = 0; ks < 2; ks++){
            #pragma unroll
            for (int nt = 0; nt < 8; nt++){
                uint2 bb = B[(ks*8 + nt)*32 + lane];
                mma16816(acc[nt], &ah[ks*4], bb.x, bb.y);
            }
        }
        __syncthreads();
    }

    // ---- full-row Z and S via quad reduce (tt) ----
    #pragma unroll
    for (int o = 1; o <= 2; o <<= 1){
        zp0 += __shfl_xor_sync(0xffffffffu, zp0, o);
        zp1 += __shfl_xor_sync(0xffffffffu, zp1, o);
        sp0 += __shfl_xor_sync(0xffffffffu, sp0, o);
        sp1 += __shfl_xor_sync(0xffffffffu, sp1, o);
    }
    float iz0 = 1.f / zp0, iz1 = 1.f / zp1;

    // ---- e_loss warp partial (quad lanes duplicate; scale by 1/4) ----
    float eterm = (sp0*iz0 + sp1*iz1) * 0.25f;
    #pragma unroll
    for (int o = 16; o > 0; o >>= 1) eterm += __shfl_xor_sync(0xffffffffu, eterm, o);
    if (lane == 0) rE[wid] = eterm;

    // ---- epilogue: normalize + bias + BN + relu ----
    const float SC = 0.9995003746877732f;   // 1/sqrt(1.001)
    size_t obase = ((size_t)(b*2048 + r0))*256 + h*64 + 2*tt;
    #pragma unroll
    for (int nt = 0; nt < 8; nt++){
        float2 bi = *(const float2*)&bias[h*64 + nt*8 + 2*tt];
        float2 o0, o1;
        o0.x = fmaxf((acc[nt][0]*iz0 + bi.x)*SC, 0.f);
        o0.y = fmaxf((acc[nt][1]*iz0 + bi.y)*SC, 0.f);
        o1.x = fmaxf((acc[nt][2]*iz1 + bi.x)*SC, 0.f);
        o1.y = fmaxf((acc[nt][3]*iz1 + bi.y)*SC, 0.f);
        *(float2*)&out[obase + nt*8]         = o0;
        *(float2*)&out[obase + nt*8 + 8*256] = o1;
    }

    // ---- deterministic block reduces ----
    rD[t] = cntD; rA[t] = cntA;
    __syncthreads();
    #pragma unroll
    for (int s = 64; s > 0; s >>= 1){
        if (t < s){ rD[t] += rD[t + s]; rA[t] += rA[t + s]; }
        __syncthreads();
    }
    if (t == 0){
        int pb = bh*32 + it;
        g_pcd[pb] = rD[0]; g_pca[pb] = rA[0];
        g_epart[pb] = rE[0] + rE[1] + rE[2] + rE[3];
        __threadfence();
        int r = atomicAdd(&g_tick, 1);
        s_last = (r == 511);
    }
    __syncthreads();

    // ---- last block finalizes aux losses (fixed-order, deterministic) ----
    if (s_last){
        __threadfence();
        int d = 0; float e = 0.f;
        #pragma unroll
        for (int k2 = 0; k2 < 4; k2++){
            int idx = t*4 + k2;                 // 4 consecutive entries, same batch
            d += g_pcd[idx] - g_pca[idx];
            e += g_epart[idx];
        }
        rD[t] = d; rF[t] = e;
        __syncthreads();
        #pragma unroll
        for (int s = 16; s > 0; s >>= 1){
            if ((t & 31) < s){ rD[t] += rD[t + s]; rF[t] += rF[t + s]; }
            __syncthreads();
        }
        if ((t & 31) == 0){
            int bb = t >> 5;
            out[OUTEL + bb]     = (float)rD[t] * (1.f/2048.f);
            out[OUTEL + 4 + bb] = rF[t] * (1.f/2048.f);
        }
    }
    #undef STAGE_B
}

// ================= launch =================
extern "C" void kernel_launch(void* const* d_in, const int* in_sizes, int n_in,
                              void* d_out, int out_size){
    const float* x       = (const float*)d_in[0];
    const float* adj     = (const float*)d_in[1];
    const float* mask    = (const float*)d_in[2];
    const float* W       = (const float*)d_in[3];
    const float* a_self  = (const float*)d_in[4];
    const float* a_neigh = (const float*)d_in[5];
    const float* bias    = (const float*)d_in[6];
    float* out = (float*)d_out;

    k_feats <<<dim3(32, 4, 4), 256>>>(x, W, a_self, a_neigh, mask);
    k_main  <<<dim3(32, 4, 4), 128>>>(adj, mask, bias, out);
}

// round 15
// speedup vs baseline: 2.8237x; 1.2232x over previous
#include <cuda_runtime.h>
#include <cuda_fp16.h>
#include <math.h>
#include <stdint.h>

typedef unsigned long long u64;
typedef unsigned int u32;
#define DINL __device__ __forceinline__

#define OUTEL  2097152            // 4*2048*256

// ---------------- scratch ----------------
static __device__ float g_Fa [32768];             // e^{sn}
static __device__ float g_Fb [32768];             // e^{0.2 sn}
static __device__ float g_thr[32768];             // e^{-ss}
static __device__ float g_Ea [32768];             // e^{ss}
static __device__ float g_Eb [32768];             // e^{0.2 ss}
static __device__ float g_epart[512];
static __device__ int   g_pcd[512];
static __device__ int   g_pca[512];
static __device__ int   g_mpart[512];
static __device__ int   g_tick;
// B fragments, K-permuted, nt-paired: [bh][jc=64][256 uint4]
// entry (ks*4+np)*32+lane = {nt=2np b0, nt=2np b1, nt=2np+1 b0, nt=2np+1 b1}
// K-permutation: lane tt2 owns j = base + 4*tt2 .. +3  (b0 = j0,j0+1 ; b1 = j0+2,j0+3)
static __device__ uint4 g_fB4[16*64*256];

// ---------------- mma.sync m16n8k16 fp16 ----------------
DINL void mma16816(float* d, const u32* a, u32 b0, u32 b1){
    asm volatile(
        "mma.sync.aligned.m16n8k16.row.col.f32.f16.f16.f32 "
        "{%0,%1,%2,%3}, {%4,%5,%6,%7}, {%8,%9}, {%0,%1,%2,%3};"
        : "+f"(d[0]), "+f"(d[1]), "+f"(d[2]), "+f"(d[3])
        : "r"(a[0]), "r"(a[1]), "r"(a[2]), "r"(a[3]), "r"(b0), "r"(b1));
}
DINL u32 pk_h2(float p0, float p1){
    __half2 hh = __floats2half2_rn(p0, p1);
    return *(u32*)&hh;
}

// ================= kernel 1: feats GEMM + scores + fp16 pack + mask scan =================
// grid (32, 4, 4) = (ntile64, h, b), 256 threads
__global__ void __launch_bounds__(256) k_feats(const float* __restrict__ x,
                                               const float* __restrict__ W,
                                               const float* __restrict__ a_self,
                                               const float* __restrict__ a_neigh,
                                               const float* __restrict__ mask){
    __shared__ float Ws[4096];
    __shared__ float Xs[64*65];
    int b = blockIdx.z, h = blockIdx.y, it = blockIdx.x, t = threadIdx.x;
    int bh = b*4 + h;
    int L = bh*32 + it;
    if (L == 0 && t == 0) g_tick = 0;
    const float* wsrc = W + h*4096;
    const float* xsrc = x + (b*2048 + it*64)*64;
    for (int e = t; e < 4096; e += 256){
        Ws[e] = wsrc[e];
        Xs[(e >> 6)*65 + (e & 63)] = xsrc[e];
    }
    __syncthreads();
    int k = t & 63, rg = t >> 6;
    float acc[16];
    #pragma unroll
    for (int r = 0; r < 16; r++) acc[r] = 0.f;
    #pragma unroll 8
    for (int f = 0; f < 64; f++){
        float wf = Ws[f*64 + k];
        #pragma unroll
        for (int r = 0; r < 16; r++) acc[r] += Xs[(rg*16 + r)*65 + f] * wf;
    }
    __syncthreads();
    #pragma unroll
    for (int r = 0; r < 16; r++) Xs[(rg*16 + r)*65 + k] = acc[r];
    __syncthreads();

    // ---- scores ----
    int wid = t >> 5, lane = t & 31;
    float as0 = a_self[h*64 + lane],  as1 = a_self[h*64 + lane + 32];
    float an0 = a_neigh[h*64 + lane], an1 = a_neigh[h*64 + lane + 32];
    #pragma unroll
    for (int rr = 0; rr < 8; rr++){
        int row = wid*8 + rr;
        float f0 = Xs[row*65 + lane], f1 = Xs[row*65 + lane + 32];
        float ss = f0*as0 + f1*as1;
        float sn = f0*an0 + f1*an1;
        #pragma unroll
        for (int o = 16; o > 0; o >>= 1){
            ss += __shfl_xor_sync(0xffffffffu, ss, o);
            sn += __shfl_xor_sync(0xffffffffu, sn, o);
        }
        if (lane == 0){
            int gr = bh*2048 + it*64 + row;
            g_thr[gr] = __expf(-ss);
            g_Ea[gr]  = __expf(ss);
            g_Eb[gr]  = __expf(0.2f*ss);
            g_Fa[gr]  = __expf(sn);
            g_Fb[gr]  = __expf(0.2f*sn);
        }
    }

    // ---- K-permuted nt-paired fragment pack: 512 uint4 (two jc tiles) ----
    uint4* dst = g_fB4 + ((size_t)bh*64 + it*2)*256;
    #pragma unroll
    for (int q = 0; q < 2; q++){
        int e = q*256 + t;                       // 0..511
        int tile = e >> 8, ee = e & 255;
        int ks = ee >> 7, np = (ee >> 5) & 3, ln = ee & 31;
        int g2 = ln >> 2, tt2 = ln & 3;
        int n0 = np*16 + g2;                     // nt=2np
        int n1 = n0 + 8;                         // nt=2np+1
        int j0 = tile*32 + ks*16 + 4*tt2;
        u32 xx = pk_h2(Xs[j0*65 + n0],     Xs[(j0+1)*65 + n0]);
        u32 yy = pk_h2(Xs[(j0+2)*65 + n0], Xs[(j0+3)*65 + n0]);
        u32 zz = pk_h2(Xs[j0*65 + n1],     Xs[(j0+1)*65 + n1]);
        u32 ww = pk_h2(Xs[(j0+2)*65 + n1], Xs[(j0+3)*65 + n1]);
        dst[(size_t)tile*256 + ee] = make_uint4(xx, yy, zz, ww);
    }

    // ---- mask nonzero scan ----
    {
        const uint4* m4 = (const uint4*)mask + (size_t)L*8192;
        u32 v = 0;
        #pragma unroll 8
        for (int q = t; q < 8192; q += 256){
            uint4 a = m4[q];
            v |= a.x | a.y | a.z | a.w;
        }
        int any = __syncthreads_or(v != 0u);
        if (t == 0) g_mpart[L] = any;
    }
}

// ================= kernel 2: full-row fused attention GEMM + final losses =================
// grid (32,4,4): x=it (64-row tile), y=h, z=b; 128 threads = 4 warps.
__global__ void __launch_bounds__(128, 4) k_main(const float* __restrict__ adj,
                                                 const float* __restrict__ mask,
                                                 const float* __restrict__ bias,
                                                 float* __restrict__ out){
    __shared__ __align__(16) uint4 BfS[2][512];   // double-buffered superchunks (16KB)
    __shared__ float FaS[2048], FbS[2048];        // 16KB
    __shared__ float rE[4];
    __shared__ float rF[128];
    __shared__ int   rD[128], rA[128];
    __shared__ int   s_last;

    int b = blockIdx.z, h = blockIdx.y, it = blockIdx.x;
    int t = threadIdx.x, wid = t >> 5, lane = t & 31;
    int g = lane >> 2, tt = lane & 3;
    int bh = b*4 + h;

    {
        const float4* fa4 = (const float4*)(g_Fa + bh*2048);
        const float4* fb4 = (const float4*)(g_Fb + bh*2048);
        #pragma unroll
        for (int q = 0; q < 4; q++){
            ((float4*)FaS)[q*128 + t] = fa4[q*128 + t];
            ((float4*)FbS)[q*128 + t] = fb4[q*128 + t];
        }
    }

    int mv = g_mpart[t] | g_mpart[t + 128] | g_mpart[t + 256] | g_mpart[t + 384];
    const bool mz = !__syncthreads_or(mv);

    int r0 = it*64 + wid*16 + g;
    float thr0 = g_thr[bh*2048 + r0], thr1 = g_thr[bh*2048 + r0 + 8];
    float Ea0  = g_Ea [bh*2048 + r0], Ea1  = g_Ea [bh*2048 + r0 + 8];
    float Eb0  = g_Eb [bh*2048 + r0], Eb1  = g_Eb [bh*2048 + r0 + 8];
    size_t row0 = ((size_t)(b*2048 + r0))*2048;
    size_t row1 = row0 + (size_t)8*2048;

    const uint4* fB = g_fB4 + (size_t)bh*64*256;

    float acc[8][4];
    #pragma unroll
    for (int nt = 0; nt < 8; nt++)
        #pragma unroll
        for (int r = 0; r < 4; r++) acc[nt][r] = 0.f;

    float zp0 = 0.f, zp1 = 0.f, sp0 = 0.f, sp1 = 0.f;
    int cntD = 0, cntA = 0;

    // stage superchunk sc (2 jc tiles = 512 uint4)
    #define STAGE(sc) do { \
        const uint4* _s = fB + (size_t)(sc)*512; \
        uint4* _d = BfS[(sc) & 1]; \
        _d[t] = _s[t]; _d[t + 128] = _s[t + 128]; \
        _d[t + 256] = _s[t + 256]; _d[t + 384] = _s[t + 384]; \
    } while(0)

    // batched adj loads for chunk c: R[0,1]=ks0 rows g,g+8; R[2,3]=ks1
    #define LOAD_ADJ(R, c) do { \
        int _c0 = (c)*32 + 4*tt; \
        R[0] = *(const float4*)(adj + row0 + _c0); \
        R[1] = *(const float4*)(adj + row1 + _c0); \
        R[2] = *(const float4*)(adj + row0 + _c0 + 16); \
        R[3] = *(const float4*)(adj + row1 + _c0 + 16); \
    } while(0)

    #define COMP(AH, R, c) do { \
        _Pragma("unroll") \
        for (int _ks = 0; _ks < 2; _ks++){ \
            int _col = (c)*32 + _ks*16 + 4*tt; \
            float4 _a0 = R[_ks*2], _a1 = R[_ks*2 + 1]; \
            float4 _fa = *(const float4*)(FaS + _col); \
            float4 _fb = *(const float4*)(FbS + _col); \
            float _w00 = (_fa.x > thr0) ? Ea0*_fa.x : Eb0*_fb.x; \
            float _w01 = (_fa.y > thr0) ? Ea0*_fa.y : Eb0*_fb.y; \
            float _w02 = (_fa.z > thr0) ? Ea0*_fa.z : Eb0*_fb.z; \
            float _w03 = (_fa.w > thr0) ? Ea0*_fa.w : Eb0*_fb.w; \
            float _w10 = (_fa.x > thr1) ? Ea1*_fa.x : Eb1*_fb.x; \
            float _w11 = (_fa.y > thr1) ? Ea1*_fa.y : Eb1*_fb.y; \
            float _w12 = (_fa.z > thr1) ? Ea1*_fa.z : Eb1*_fb.z; \
            float _w13 = (_fa.w > thr1) ? Ea1*_fa.w : Eb1*_fb.w; \
            if (!mz){ \
                float4 _m0 = *(const float4*)(mask + row0 + _col); \
                float4 _m1 = *(const float4*)(mask + row1 + _col); \
                _w00 *= __expf(_m0.x); _w01 *= __expf(_m0.y); \
                _w02 *= __expf(_m0.z); _w03 *= __expf(_m0.w); \
                _w10 *= __expf(_m1.x); _w11 *= __expf(_m1.y); \
                _w12 *= __expf(_m1.z); _w13 *= __expf(_m1.w); \
            } \
            float _p00 = _a0.x*_w00, _p01 = _a0.y*_w01, _p02 = _a0.z*_w02, _p03 = _a0.w*_w03; \
            float _p10 = _a1.x*_w10, _p11 = _a1.y*_w11, _p12 = _a1.z*_w12, _p13 = _a1.w*_w13; \
            zp0 += (_w00 + _w01) + (_w02 + _w03); \
            zp1 += (_w10 + _w11) + (_w12 + _w13); \
            sp0 += (fabsf(_p00) + fabsf(_p01)) + (fabsf(_p02) + fabsf(_p03)); \
            sp1 += (fabsf(_p10) + fabsf(_p11)) + (fabsf(_p12) + fabsf(_p13)); \
            cntD += (_p00 != 0.f) + (_p01 != 0.f) + (_p02 != 0.f) + (_p03 != 0.f) \
                  + (_p10 != 0.f) + (_p11 != 0.f) + (_p12 != 0.f) + (_p13 != 0.f); \
            cntA += (_a0.x != 0.f) + (_a0.y != 0.f) + (_a0.z != 0.f) + (_a0.w != 0.f) \
                  + (_a1.x != 0.f) + (_a1.y != 0.f) + (_a1.z != 0.f) + (_a1.w != 0.f); \
            AH[_ks*4 + 0] = pk_h2(_p00, _p01); \
            AH[_ks*4 + 1] = pk_h2(_p10, _p11); \
            AH[_ks*4 + 2] = pk_h2(_p02, _p03); \
            AH[_ks*4 + 3] = pk_h2(_p12, _p13); \
        } \
    } while(0)

    #define MMA_CHUNK(sc, c, AH) do { \
        const uint4* _B = BfS[(sc) & 1] + ((c) & 1)*256; \
        _Pragma("unroll") \
        for (int _ks = 0; _ks < 2; _ks++){ \
            _Pragma("unroll") \
            for (int _np = 0; _np < 4; _np++){ \
                uint4 _bb = _B[(_ks*4 + _np)*32 + lane]; \
                mma16816(acc[2*_np],     &AH[_ks*4], _bb.x, _bb.y); \
                mma16816(acc[2*_np + 1], &AH[_ks*4], _bb.z, _bb.w); \
            } \
        } \
    } while(0)

    STAGE(0);
    __syncthreads();

    #pragma unroll 1
    for (int sc = 0; sc < 32; sc++){
        if (sc + 1 < 32) STAGE(sc + 1);
        int c0 = 2*sc, c1 = c0 + 1;
        float4 RA[4], RB[4];
        LOAD_ADJ(RA, c0);
        LOAD_ADJ(RB, c1);
        u32 ah[8];
        COMP(ah, RA, c0);
        MMA_CHUNK(sc, c0, ah);
        COMP(ah, RB, c1);
        MMA_CHUNK(sc, c1, ah);
        __syncthreads();
    }

    // ---- full-row Z and S via quad reduce (tt) ----
    #pragma unroll
    for (int o = 1; o <= 2; o <<= 1){
        zp0 += __shfl_xor_sync(0xffffffffu, zp0, o);
        zp1 += __shfl_xor_sync(0xffffffffu, zp1, o);
        sp0 += __shfl_xor_sync(0xffffffffu, sp0, o);
        sp1 += __shfl_xor_sync(0xffffffffu, sp1, o);
    }
    float iz0 = 1.f / zp0, iz1 = 1.f / zp1;

    // ---- e_loss warp partial (quad lanes duplicate; scale by 1/4) ----
    float eterm = (sp0*iz0 + sp1*iz1) * 0.25f;
    #pragma unroll
    for (int o = 16; o > 0; o >>= 1) eterm += __shfl_xor_sync(0xffffffffu, eterm, o);
    if (lane == 0) rE[wid] = eterm;

    // ---- epilogue: normalize + bias + BN + relu ----
    const float SC = 0.9995003746877732f;   // 1/sqrt(1.001)
    size_t obase = ((size_t)(b*2048 + r0))*256 + h*64 + 2*tt;
    #pragma unroll
    for (int nt = 0; nt < 8; nt++){
        float2 bi = *(const float2*)&bias[h*64 + nt*8 + 2*tt];
        float2 o0, o1;
        o0.x = fmaxf((acc[nt][0]*iz0 + bi.x)*SC, 0.f);
        o0.y = fmaxf((acc[nt][1]*iz0 + bi.y)*SC, 0.f);
        o1.x = fmaxf((acc[nt][2]*iz1 + bi.x)*SC, 0.f);
        o1.y = fmaxf((acc[nt][3]*iz1 + bi.y)*SC, 0.f);
        *(float2*)&out[obase + nt*8]         = o0;
        *(float2*)&out[obase + nt*8 + 8*256] = o1;
    }

    // ---- deterministic block reduces ----
    rD[t] = cntD; rA[t] = cntA;
    __syncthreads();
    #pragma unroll
    for (int s = 64; s > 0; s >>= 1){
        if (t < s){ rD[t] += rD[t + s]; rA[t] += rA[t + s]; }
        __syncthreads();
    }
    if (t == 0){
        int pb = bh*32 + it;
        g_pcd[pb] = rD[0]; g_pca[pb] = rA[0];
        g_epart[pb] = rE[0] + rE[1] + rE[2] + rE[3];
        __threadfence();
        int r = atomicAdd(&g_tick, 1);
        s_last = (r == 511);
    }
    __syncthreads();

    // ---- last block finalizes aux losses ----
    if (s_last){
        __threadfence();
        int d = 0; float e = 0.f;
        #pragma unroll
        for (int k2 = 0; k2 < 4; k2++){
            int idx = t*4 + k2;
            d += g_pcd[idx] - g_pca[idx];
            e += g_epart[idx];
        }
        rD[t] = d; rF[t] = e;
        __syncthreads();
        #pragma unroll
        for (int s = 16; s > 0; s >>= 1){
            if ((t & 31) < s){ rD[t] += rD[t + s]; rF[t] += rF[t + s]; }
            __syncthreads();
        }
        if ((t & 31) == 0){
            int bb = t >> 5;
            out[OUTEL + bb]     = (float)rD[t] * (1.f/2048.f);
            out[OUTEL + 4 + bb] = rF[t] * (1.f/2048.f);
        }
    }
    #undef STAGE
    #undef LOAD_ADJ
    #undef COMP
    #undef MMA_CHUNK
}

// ================= launch =================
extern "C" void kernel_launch(void* const* d_in, const int* in_sizes, int n_in,
                              void* d_out, int out_size){
    const float* x       = (const float*)d_in[0];
    const float* adj     = (const float*)d_in[1];
    const float* mask    = (const float*)d_in[2];
    const float* W       = (const float*)d_in[3];
    const float* a_self  = (const float*)d_in[4];
    const float* a_neigh = (const float*)d_in[5];
    const float* bias    = (const float*)d_in[6];
    float* out = (float*)d_out;

    k_feats <<<dim3(32, 4, 4), 256>>>(x, W, a_self, a_neigh, mask);
    k_main  <<<dim3(32, 4, 4), 128>>>(adj, mask, bias, out);
}